// round 1
// baseline (speedup 1.0000x reference)
#include <cuda_runtime.h>

#define N_TOK 98
#define DIM   128
#define HEADS 4
#define HDIM  32
#define NWIN  64
#define SCALE 0.17677669529663687f   // 1/sqrt(32)

// ---- shared memory layout (float offsets) ----
#define XS_STRIDE 132
#define XS_OFF    0                       // xs [112][132]  -> later reused as probs
#define QS_STRIDE 132
#define QS_OFF    (112*132)               // qs [112][132]  (rows 98..111 kept zero) -> later O
#define KT_STRIDE 99
#define KT_OFF    (QS_OFF + 112*132)      // kt [128][99]   (K transposed: [c][m])
#define VT_OFF    (KT_OFF + 128*99)       // vt [128][99]   (V transposed: [c][m])
#define SMEM_FLOATS (VT_OFF + 128*99)     // 54912 floats = 219648 bytes
#define PROBS_OFF 0                       // probs [36][100][4] fp32, reuses XS region
#define PROBS_ROW 400                     // 100 * 4 floats per local row

static __device__ __forceinline__ float warp_max(float v) {
#pragma unroll
    for (int o = 16; o > 0; o >>= 1) v = fmaxf(v, __shfl_xor_sync(0xffffffffu, v, o));
    return v;
}
static __device__ __forceinline__ float warp_sum(float v) {
#pragma unroll
    for (int o = 16; o > 0; o >>= 1) v += __shfl_xor_sync(0xffffffffu, v, o);
    return v;
}

__global__ __launch_bounds__(256, 1)
void win_attn_kernel(const float* __restrict__ x,
                     const float* __restrict__ mask,
                     const float* __restrict__ qkv_w,
                     const float* __restrict__ qkv_b,
                     const float* __restrict__ proj_w,
                     const float* __restrict__ proj_b,
                     const float* __restrict__ bias_table,
                     const int*   __restrict__ rel_idx,
                     float* __restrict__ out)
{
    extern __shared__ float sm[];
    const int b    = blockIdx.x;
    const int tid  = threadIdx.x;
    const int lane = tid & 31;
    const int warp = tid >> 5;
    const int tx   = tid & 15;     // output-column group (j)
    const int ty   = tid >> 4;     // output-row group (n)
    const int win  = b & (NWIN - 1);

    // ---------------- phase 0: stage x into smem, zero padding rows ----------------
    {
        const float4* xg = reinterpret_cast<const float4*>(x + (size_t)b * N_TOK * DIM);
        for (int idx = tid; idx < N_TOK * 32; idx += 256) {
            int r = idx >> 5, c4 = idx & 31;
            *reinterpret_cast<float4*>(&sm[XS_OFF + r * XS_STRIDE + 4 * c4]) = xg[idx];
        }
        // zero xs rows 98..111 and qs rows 98..111 (GEMM padding rows)
        float4 z = make_float4(0.f, 0.f, 0.f, 0.f);
        for (int idx = tid; idx < 14 * 32; idx += 256) {
            int r = 98 + (idx >> 5), c4 = idx & 31;
            *reinterpret_cast<float4*>(&sm[XS_OFF + r * XS_STRIDE + 4 * c4]) = z;
            *reinterpret_cast<float4*>(&sm[QS_OFF + r * QS_STRIDE + 4 * c4]) = z;
        }
    }
    __syncthreads();

    // ---------------- phase 1: QKV GEMM  (per thread: 7 rows x 8 cols) -------------
    {
        const int n0 = ty * 7;   // rows n0..n0+6 (ty=14,15 compute on zero rows, stores guarded)
#pragma unroll
        for (int s = 0; s < 3; s++) {
            const float* wp = qkv_w + s * DIM * DIM;
            float acc[7][8];
#pragma unroll
            for (int k = 0; k < 8; k++) {
                float bv = qkv_b[s * DIM + tx + 16 * k];
#pragma unroll
                for (int i = 0; i < 7; i++) acc[i][k] = bv;
            }
#pragma unroll 4
            for (int c4 = 0; c4 < 32; c4++) {
                float4 xv[7], wv[8];
#pragma unroll
                for (int i = 0; i < 7; i++)
                    xv[i] = *reinterpret_cast<const float4*>(&sm[XS_OFF + (n0 + i) * XS_STRIDE + 4 * c4]);
#pragma unroll
                for (int k = 0; k < 8; k++)
                    wv[k] = *reinterpret_cast<const float4*>(&wp[(tx + 16 * k) * DIM + 4 * c4]);
#pragma unroll
                for (int i = 0; i < 7; i++)
#pragma unroll
                    for (int k = 0; k < 8; k++) {
                        acc[i][k] = fmaf(xv[i].x, wv[k].x, acc[i][k]);
                        acc[i][k] = fmaf(xv[i].y, wv[k].y, acc[i][k]);
                        acc[i][k] = fmaf(xv[i].z, wv[k].z, acc[i][k]);
                        acc[i][k] = fmaf(xv[i].w, wv[k].w, acc[i][k]);
                    }
            }
            if (s == 0) {            // Q: row-major, pre-scaled
#pragma unroll
                for (int i = 0; i < 7; i++) {
                    int n = n0 + i;
                    if (n < N_TOK) {
#pragma unroll
                        for (int k = 0; k < 8; k++)
                            sm[QS_OFF + n * QS_STRIDE + tx + 16 * k] = acc[i][k] * SCALE;
                    }
                }
            } else {                 // K,V: transposed [c][m]
                int off = (s == 1) ? KT_OFF : VT_OFF;
#pragma unroll
                for (int i = 0; i < 7; i++) {
                    int n = n0 + i;
                    if (n < N_TOK) {
#pragma unroll
                        for (int k = 0; k < 8; k++)
                            sm[off + (tx + 16 * k) * KT_STRIDE + n] = acc[i][k];
                    }
                }
            }
        }
    }
    __syncthreads();

    // ---------------- phase 2: attention in 3 row-phases ---------------------------
    const float* maskp = mask + (size_t)win * N_TOK * N_TOK;

#pragma unroll 1
    for (int ph = 0; ph < 3; ph++) {
        const int base = (ph == 0) ? 0 : (ph == 1) ? 36 : 72;
        const int g0   = base >> 2;                 // 0, 9, 18
        const int ng   = (ph == 2) ? 7 : 9;         // 4-row groups this phase

        // ---- scores + softmax: warp item = (head, 4-row group) ----
        for (int item = warp; item < ng * HEADS; item += 8) {
            const int h  = item & 3;
            const int g  = g0 + (item >> 2);
            const int n0 = g * 4;

            float s[4][4];
#pragma unroll
            for (int r = 0; r < 4; r++)
#pragma unroll
                for (int k = 0; k < 4; k++) s[r][k] = 0.f;

#pragma unroll 4
            for (int d = 0; d < 32; d++) {
                float kv[4];
#pragma unroll
                for (int k = 0; k < 4; k++)
                    kv[k] = sm[KT_OFF + (h * 32 + d) * KT_STRIDE + lane + 32 * k];
#pragma unroll
                for (int r = 0; r < 4; r++) {
                    float qv = sm[QS_OFF + (n0 + r) * QS_STRIDE + h * 32 + d];
#pragma unroll
                    for (int k = 0; k < 4; k++) s[r][k] = fmaf(qv, kv[k], s[r][k]);
                }
            }

#pragma unroll
            for (int r = 0; r < 4; r++) {
                const int n = n0 + r;
                if (n >= N_TOK) break;
                float l[4];
#pragma unroll
                for (int k = 0; k < 4; k++) {
                    int m = lane + 32 * k;
                    if (m < N_TOK) {
                        int   rel = rel_idx[n * N_TOK + m];
                        float bv  = bias_table[rel * HEADS + h];
                        float mv  = maskp[n * N_TOK + m];
                        l[k] = s[r][k] + bv + mv;
                    } else {
                        l[k] = -1e30f;
                    }
                }
                float mx = fmaxf(fmaxf(l[0], l[1]), fmaxf(l[2], l[3]));
                mx = warp_max(mx);
                float e[4], sum = 0.f;
#pragma unroll
                for (int k = 0; k < 4; k++) { e[k] = __expf(l[k] - mx); sum += e[k]; }
                sum = warp_sum(sum);
                float inv = 1.0f / sum;
#pragma unroll
                for (int k = 0; k < 4; k++) {
                    int m = lane + 32 * k;
                    if (m < N_TOK)
                        sm[PROBS_OFF + (n - base) * PROBS_ROW + m * HEADS + h] = e[k] * inv;
                }
            }
        }
        __syncthreads();

        // ---- AV: warp item = 4-row group; lane covers c = lane + 32h ----
        for (int g = g0 + warp; g < g0 + ng; g += 8) {
            const int n0 = g * 4;
            float acc[4][4];
#pragma unroll
            for (int r = 0; r < 4; r++)
#pragma unroll
                for (int hh = 0; hh < 4; hh++) acc[r][hh] = 0.f;

#pragma unroll 2
            for (int m = 0; m < N_TOK; m++) {
                float vv[4];
#pragma unroll
                for (int hh = 0; hh < 4; hh++)
                    vv[hh] = sm[VT_OFF + (lane + 32 * hh) * KT_STRIDE + m];
#pragma unroll
                for (int r = 0; r < 4; r++) {
                    float4 p = *reinterpret_cast<const float4*>(
                        &sm[PROBS_OFF + (n0 - base + r) * PROBS_ROW + m * HEADS]);
                    acc[r][0] = fmaf(p.x, vv[0], acc[r][0]);
                    acc[r][1] = fmaf(p.y, vv[1], acc[r][1]);
                    acc[r][2] = fmaf(p.z, vv[2], acc[r][2]);
                    acc[r][3] = fmaf(p.w, vv[3], acc[r][3]);
                }
            }
#pragma unroll
            for (int r = 0; r < 4; r++) {
                int n = n0 + r;
                if (n < N_TOK) {
#pragma unroll
                    for (int hh = 0; hh < 4; hh++)
                        sm[QS_OFF + n * QS_STRIDE + lane + 32 * hh] = acc[r][hh];
                }
            }
        }
        __syncthreads();
    }

    // ---------------- phase 3: output projection ----------------------------------
    {
        const int n0 = ty * 7;
        float acc[7][8];
#pragma unroll
        for (int k = 0; k < 8; k++) {
            float bv = proj_b[tx + 16 * k];
#pragma unroll
            for (int i = 0; i < 7; i++) acc[i][k] = bv;
        }
#pragma unroll 4
        for (int c4 = 0; c4 < 32; c4++) {
            float4 xv[7], wv[8];
#pragma unroll
            for (int i = 0; i < 7; i++)
                xv[i] = *reinterpret_cast<const float4*>(&sm[QS_OFF + (n0 + i) * QS_STRIDE + 4 * c4]);
#pragma unroll
            for (int k = 0; k < 8; k++)
                wv[k] = *reinterpret_cast<const float4*>(&proj_w[(tx + 16 * k) * DIM + 4 * c4]);
#pragma unroll
            for (int i = 0; i < 7; i++)
#pragma unroll
                for (int k = 0; k < 8; k++) {
                    acc[i][k] = fmaf(xv[i].x, wv[k].x, acc[i][k]);
                    acc[i][k] = fmaf(xv[i].y, wv[k].y, acc[i][k]);
                    acc[i][k] = fmaf(xv[i].z, wv[k].z, acc[i][k]);
                    acc[i][k] = fmaf(xv[i].w, wv[k].w, acc[i][k]);
                }
        }
        float* op = out + (size_t)b * N_TOK * DIM;
#pragma unroll
        for (int i = 0; i < 7; i++) {
            int n = n0 + i;
            if (n < N_TOK) {
#pragma unroll
                for (int k = 0; k < 8; k++)
                    op[n * DIM + tx + 16 * k] = acc[i][k];
            }
        }
    }
}

extern "C" void kernel_launch(void* const* d_in, const int* in_sizes, int n_in,
                              void* d_out, int out_size)
{
    const float* x          = (const float*)d_in[0];
    const float* mask       = (const float*)d_in[1];
    const float* qkv_w      = (const float*)d_in[2];
    const float* qkv_b      = (const float*)d_in[3];
    const float* proj_w     = (const float*)d_in[4];
    const float* proj_b     = (const float*)d_in[5];
    const float* bias_table = (const float*)d_in[6];
    const int*   rel_idx    = (const int*)d_in[7];
    float*       out        = (float*)d_out;

    const int B = in_sizes[0] / (N_TOK * DIM);
    const size_t smem_bytes = (size_t)SMEM_FLOATS * sizeof(float);   // 219648

    cudaFuncSetAttribute(win_attn_kernel,
                         cudaFuncAttributeMaxDynamicSharedMemorySize,
                         (int)smem_bytes);

    win_attn_kernel<<<B, 256, smem_bytes>>>(x, mask, qkv_w, qkv_b,
                                            proj_w, proj_b, bias_table,
                                            rel_idx, out);
}

// round 2
// speedup vs baseline: 2.2618x; 2.2618x over previous
#include <cuda_runtime.h>

#define N_TOK 98
#define DIM   128
#define HEADS 4
#define NWIN  64
#define SCALE 0.17677669529663687f   // 1/sqrt(32)

// ---- shared memory layout (float offsets) ----
#define XS_STRIDE 132
#define XS_OFF    0                       // xs [98][132] -> probs region later
#define QS_OFF    12936                   // qs [98][132] (Q, later O)
#define KT_OFF    (QS_OFF + 12936)        // kt [128][99]
#define VT_OFF    (KT_OFF + 12672)        // vt [128][99]
#define WS_OFF    (VT_OFF + 12672)        // weight staging [128][36]
#define WS_STRIDE 36
#define SMEM_FLOATS (WS_OFF + 128*36)     // 55824 floats = 223296 B

#define PROBS_OFF 0
#define PROBS_H   3200                    // 32 rows * 100
#define PROBS_R   100

__device__ float g_comb[NWIN * HEADS * N_TOK * N_TOK];   // bias+mask, 9.8 MB

static __device__ __forceinline__ float warp_max(float v) {
#pragma unroll
    for (int o = 16; o > 0; o >>= 1) v = fmaxf(v, __shfl_xor_sync(0xffffffffu, v, o));
    return v;
}
static __device__ __forceinline__ float warp_sum(float v) {
#pragma unroll
    for (int o = 16; o > 0; o >>= 1) v += __shfl_xor_sync(0xffffffffu, v, o);
    return v;
}

// One 98x128 @ 128x128 GEMM: input rows in smem at in_off (stride 132),
// weights [128 out][128 in] row-major from gmem staged through WS.
// Thread (tx,ty): rows 3ty..3ty+2, cols tx+16k (k=0..7). Warp 0 also does rows 96,97.
static __device__ __forceinline__ void gemm128(float* sm, int in_off,
                                               const float* __restrict__ w,
                                               float acc[3][8], float acc3[8],
                                               int tx, int ty, int tid)
{
#pragma unroll 1
    for (int ch = 0; ch < 4; ch++) {
        __syncthreads();
        // stage weight chunk: cols 0..127, c in [32ch, 32ch+32)
#pragma unroll
        for (int rr = 0; rr < 2; rr++) {
            int j   = tid + rr * 512;
            int col = j >> 3;
            int cc4 = j & 7;
            float4 v = *reinterpret_cast<const float4*>(&w[col * DIM + ch * 32 + cc4 * 4]);
            *reinterpret_cast<float4*>(&sm[WS_OFF + col * WS_STRIDE + cc4 * 4]) = v;
        }
        __syncthreads();
#pragma unroll
        for (int cc4 = 0; cc4 < 8; cc4++) {
            float4 wv[8];
#pragma unroll
            for (int k = 0; k < 8; k++)
                wv[k] = *reinterpret_cast<const float4*>(&sm[WS_OFF + (tx + 16 * k) * WS_STRIDE + cc4 * 4]);
            float4 xv[3];
#pragma unroll
            for (int i = 0; i < 3; i++)
                xv[i] = *reinterpret_cast<const float4*>(&sm[in_off + (3 * ty + i) * XS_STRIDE + ch * 32 + cc4 * 4]);
#pragma unroll
            for (int i = 0; i < 3; i++)
#pragma unroll
                for (int k = 0; k < 8; k++) {
                    acc[i][k] = fmaf(xv[i].x, wv[k].x, acc[i][k]);
                    acc[i][k] = fmaf(xv[i].y, wv[k].y, acc[i][k]);
                    acc[i][k] = fmaf(xv[i].z, wv[k].z, acc[i][k]);
                    acc[i][k] = fmaf(xv[i].w, wv[k].w, acc[i][k]);
                }
            if (ty < 2) {   // warp 0 handles rows 96,97 (uniform per warp)
                float4 xt = *reinterpret_cast<const float4*>(&sm[in_off + (96 + ty) * XS_STRIDE + ch * 32 + cc4 * 4]);
#pragma unroll
                for (int k = 0; k < 8; k++) {
                    acc3[k] = fmaf(xt.x, wv[k].x, acc3[k]);
                    acc3[k] = fmaf(xt.y, wv[k].y, acc3[k]);
                    acc3[k] = fmaf(xt.z, wv[k].z, acc3[k]);
                    acc3[k] = fmaf(xt.w, wv[k].w, acc3[k]);
                }
            }
        }
    }
}

__global__ void comb_kernel(const float* __restrict__ mask,
                            const float* __restrict__ bias_table,
                            const int*   __restrict__ rel_idx)
{
    int idx = blockIdx.x * blockDim.x + threadIdx.x;
    const int total = NWIN * HEADS * N_TOK * N_TOK;
    if (idx >= total) return;
    int w   = idx / (HEADS * N_TOK * N_TOK);
    int rem = idx - w * (HEADS * N_TOK * N_TOK);
    int h   = rem / (N_TOK * N_TOK);
    int nm  = rem - h * (N_TOK * N_TOK);
    g_comb[idx] = bias_table[rel_idx[nm] * HEADS + h] + mask[w * (N_TOK * N_TOK) + nm];
}

__global__ __launch_bounds__(512, 1)
void win_attn_kernel(const float* __restrict__ x,
                     const float* __restrict__ qkv_w,
                     const float* __restrict__ qkv_b,
                     const float* __restrict__ proj_w,
                     const float* __restrict__ proj_b,
                     float* __restrict__ out)
{
    extern __shared__ float sm[];
    const int b    = blockIdx.x;
    const int tid  = threadIdx.x;
    const int lane = tid & 31;
    const int warp = tid >> 5;
    const int tx   = tid & 15;
    const int ty   = tid >> 4;          // 0..31
    const int win  = b & (NWIN - 1);

    // ---------------- stage x ----------------
    {
        const float4* xg = reinterpret_cast<const float4*>(x + (size_t)b * N_TOK * DIM);
        for (int i = tid; i < N_TOK * 32; i += 512) {
            int r = i >> 5, c = i & 31;
            *reinterpret_cast<float4*>(&sm[XS_OFF + r * XS_STRIDE + 4 * c]) = xg[i];
        }
    }
    // gemm128's leading __syncthreads() covers the hazard

    // ---------------- QKV GEMMs ----------------
#pragma unroll 1
    for (int s = 0; s < 3; s++) {
        float acc[3][8], acc3[8];
#pragma unroll
        for (int k = 0; k < 8; k++) {
            float bv = qkv_b[s * DIM + tx + 16 * k];
            acc3[k] = bv;
#pragma unroll
            for (int i = 0; i < 3; i++) acc[i][k] = bv;
        }
        gemm128(sm, XS_OFF, qkv_w + s * DIM * DIM, acc, acc3, tx, ty, tid);
        __syncthreads();
        if (s == 0) {   // Q row-major, pre-scaled
#pragma unroll
            for (int i = 0; i < 3; i++)
#pragma unroll
                for (int k = 0; k < 8; k++)
                    sm[QS_OFF + (3 * ty + i) * XS_STRIDE + tx + 16 * k] = acc[i][k] * SCALE;
            if (ty < 2)
#pragma unroll
                for (int k = 0; k < 8; k++)
                    sm[QS_OFF + (96 + ty) * XS_STRIDE + tx + 16 * k] = acc3[k] * SCALE;
        } else {        // K,V transposed [c][m]
            int off = (s == 1) ? KT_OFF : VT_OFF;
#pragma unroll
            for (int i = 0; i < 3; i++)
#pragma unroll
                for (int k = 0; k < 8; k++)
                    sm[off + (tx + 16 * k) * 99 + 3 * ty + i] = acc[i][k];
            if (ty < 2)
#pragma unroll
                for (int k = 0; k < 8; k++)
                    sm[off + (tx + 16 * k) * 99 + 96 + ty] = acc3[k];
        }
    }
    __syncthreads();

    // ---------------- attention: 4 phases of up to 32 rows ----------------
    const float* combw = g_comb + (size_t)(win * HEADS) * N_TOK * N_TOK;

#pragma unroll 1
    for (int ph = 0; ph < 4; ph++) {
        const int base = ph * 32;

        // ---- scores + softmax: warp -> (g = warp>>2 : 8 rows, h = warp&3) ----
        {
            const int g  = warp >> 2;
            const int h  = warp & 3;
            const int n0 = base + g * 8;
            if (n0 < N_TOK) {
                float s[8][4];
#pragma unroll
                for (int r = 0; r < 8; r++)
#pragma unroll
                    for (int k = 0; k < 4; k++) s[r][k] = 0.f;

#pragma unroll 1
                for (int d4 = 0; d4 < 8; d4++) {
                    float4 q4[8];
#pragma unroll
                    for (int r = 0; r < 8; r++)
                        q4[r] = *reinterpret_cast<const float4*>(&sm[QS_OFF + (n0 + r) * XS_STRIDE + h * 32 + d4 * 4]);
#pragma unroll
                    for (int dd = 0; dd < 4; dd++) {
                        int d = d4 * 4 + dd;
                        float kv[4];
#pragma unroll
                        for (int k = 0; k < 4; k++)
                            kv[k] = sm[KT_OFF + (h * 32 + d) * 99 + lane + 32 * k];
#pragma unroll
                        for (int r = 0; r < 8; r++) {
                            float qv = (dd == 0) ? q4[r].x : (dd == 1) ? q4[r].y : (dd == 2) ? q4[r].z : q4[r].w;
#pragma unroll
                            for (int k = 0; k < 4; k++) s[r][k] = fmaf(qv, kv[k], s[r][k]);
                        }
                    }
                }
#pragma unroll 1
                for (int r = 0; r < 8; r++) {
                    const int n = n0 + r;
                    if (n >= N_TOK) break;
                    const float* cp = combw + ((size_t)h * N_TOK + n) * N_TOK;
                    float l[4];
#pragma unroll
                    for (int k = 0; k < 4; k++) {
                        int m = lane + 32 * k;
                        l[k] = (m < N_TOK) ? (s[r][k] + cp[m]) : -1e30f;
                    }
                    float mx = warp_max(fmaxf(fmaxf(l[0], l[1]), fmaxf(l[2], l[3])));
                    float e[4], sum = 0.f;
#pragma unroll
                    for (int k = 0; k < 4; k++) { e[k] = __expf(l[k] - mx); sum += e[k]; }
                    sum = warp_sum(sum);
                    float inv = __fdividef(1.0f, sum);
#pragma unroll
                    for (int k = 0; k < 4; k++) {
                        int m = lane + 32 * k;
                        if (m < N_TOK)
                            sm[PROBS_OFF + h * PROBS_H + (n - base) * PROBS_R + m] = e[k] * inv;
                    }
                }
            }
        }
        __syncthreads();

        // ---- AV: warp -> (g : 8 rows, h); lane covers channel c = h*32+lane ----
        {
            const int g  = warp >> 2;
            const int h  = warp & 3;
            const int n0 = base + g * 8;
            if (n0 < N_TOK) {
                const int c = h * 32 + lane;
                const float* vb = &sm[VT_OFF + c * 99];
                const float* pb = &sm[PROBS_OFF + h * PROBS_H + (n0 - base) * PROBS_R];
                float acc[8];
#pragma unroll
                for (int r = 0; r < 8; r++) acc[r] = 0.f;
#pragma unroll 4
                for (int mc = 0; mc < 24; mc++) {
                    float v0 = vb[4 * mc + 0], v1 = vb[4 * mc + 1];
                    float v2 = vb[4 * mc + 2], v3 = vb[4 * mc + 3];
#pragma unroll
                    for (int r = 0; r < 8; r++) {
                        float4 p = *reinterpret_cast<const float4*>(&pb[r * PROBS_R + 4 * mc]);
                        acc[r] = fmaf(p.x, v0, acc[r]);
                        acc[r] = fmaf(p.y, v1, acc[r]);
                        acc[r] = fmaf(p.z, v2, acc[r]);
                        acc[r] = fmaf(p.w, v3, acc[r]);
                    }
                }
                float v96 = vb[96], v97 = vb[97];
#pragma unroll
                for (int r = 0; r < 8; r++) {
                    acc[r] = fmaf(pb[r * PROBS_R + 96], v96, acc[r]);
                    acc[r] = fmaf(pb[r * PROBS_R + 97], v97, acc[r]);
                    int n = n0 + r;
                    if (n < N_TOK) sm[QS_OFF + n * XS_STRIDE + c] = acc[r];
                }
            }
        }
        __syncthreads();
    }

    // ---------------- output projection ----------------
    {
        float acc[3][8], acc3[8];
#pragma unroll
        for (int k = 0; k < 8; k++) {
            float bv = proj_b[tx + 16 * k];
            acc3[k] = bv;
#pragma unroll
            for (int i = 0; i < 3; i++) acc[i][k] = bv;
        }
        gemm128(sm, QS_OFF, proj_w, acc, acc3, tx, ty, tid);
        float* op = out + (size_t)b * N_TOK * DIM;
#pragma unroll
        for (int i = 0; i < 3; i++)
#pragma unroll
            for (int k = 0; k < 8; k++)
                op[(3 * ty + i) * DIM + tx + 16 * k] = acc[i][k];
        if (ty < 2)
#pragma unroll
            for (int k = 0; k < 8; k++)
                op[(96 + ty) * DIM + tx + 16 * k] = acc3[k];
    }
}

extern "C" void kernel_launch(void* const* d_in, const int* in_sizes, int n_in,
                              void* d_out, int out_size)
{
    const float* x          = (const float*)d_in[0];
    const float* mask       = (const float*)d_in[1];
    const float* qkv_w      = (const float*)d_in[2];
    const float* qkv_b      = (const float*)d_in[3];
    const float* proj_w     = (const float*)d_in[4];
    const float* proj_b     = (const float*)d_in[5];
    const float* bias_table = (const float*)d_in[6];
    const int*   rel_idx    = (const int*)d_in[7];
    float*       out        = (float*)d_out;

    const int B = in_sizes[0] / (N_TOK * DIM);

    // precompute bias+mask table
    {
        const int total = NWIN * HEADS * N_TOK * N_TOK;
        comb_kernel<<<(total + 255) / 256, 256>>>(mask, bias_table, rel_idx);
    }

    const size_t smem_bytes = (size_t)SMEM_FLOATS * sizeof(float);   // 223296
    cudaFuncSetAttribute(win_attn_kernel,
                         cudaFuncAttributeMaxDynamicSharedMemorySize,
                         (int)smem_bytes);

    win_attn_kernel<<<B, 512, smem_bytes>>>(x, qkv_w, qkv_b, proj_w, proj_b, out);
}

// round 4
// speedup vs baseline: 3.1575x; 1.3960x over previous
#include <cuda_runtime.h>
#include <cuda_bf16.h>
#include <cstdint>

#define N_TOK 98
#define DIM   128
#define HEADS 4
#define NWIN  64
#define SCALE 0.17677669529663687f

#define MAX_B    2048
#define MAX_MTOT (MAX_B * N_TOK)          // 200704

__device__ float g_qkv[(size_t)MAX_MTOT * 384];
__device__ float g_o[(size_t)MAX_MTOT * 128];
__device__ float g_comb[NWIN * HEADS * N_TOK * N_TOK];

// ======================= helpers =======================
static __device__ __forceinline__ uint32_t smem_u32(const void* p) {
    uint32_t a;
    asm("{ .reg .u64 t; cvta.to.shared.u64 t, %1; cvt.u32.u64 %0, t; }" : "=r"(a) : "l"(p));
    return a;
}
#define LDSM_X4(r0, r1, r2, r3, addr)                                          \
    asm volatile("ldmatrix.sync.aligned.m8n8.x4.shared.b16 {%0,%1,%2,%3}, [%4];" \
                 : "=r"(r0), "=r"(r1), "=r"(r2), "=r"(r3) : "r"(addr))
#define MMA_BF16(c, a, b0, b1)                                                 \
    asm volatile("mma.sync.aligned.m16n8k16.row.col.f32.bf16.bf16.f32 "        \
                 "{%0,%1,%2,%3}, {%4,%5,%6,%7}, {%8,%9}, {%0,%1,%2,%3};"       \
                 : "+f"((c)[0]), "+f"((c)[1]), "+f"((c)[2]), "+f"((c)[3])      \
                 : "r"((a)[0]), "r"((a)[1]), "r"((a)[2]), "r"((a)[3]),         \
                   "r"(b0), "r"(b1))

static __device__ __forceinline__ void bf16split(float a, __nv_bfloat16& h, __nv_bfloat16& l) {
    h = __float2bfloat16_rn(a);
    l = __float2bfloat16_rn(a - __bfloat162float(h));
}

// ======================= bf16x3 GEMM: Out[M,N] = A[M,128] @ W[N,128]^T + bias =======================
#define G_AHI 0
#define G_ALO 17408
#define G_WHI 34816
#define G_WLO 43520
#define G_SMEM_BYTES (52224 * 2)     // 104448

__global__ __launch_bounds__(256)
void gemm_bf16x3(const float* __restrict__ A,
                 const float* __restrict__ W,
                 const float* __restrict__ bias,
                 float* __restrict__ Out,
                 int Nout, int Mtot)
{
    extern __shared__ __nv_bfloat16 sb[];
    const uint32_t sbase = smem_u32(sb);
    const int tid  = threadIdx.x;
    const int lane = tid & 31;
    const int warp = tid >> 5;
    const int wm   = warp & 3;
    const int wn   = warp >> 2;
    const long row0 = (long)blockIdx.x * 128;
    const int  col0 = blockIdx.y * 64;

    // ---- stage A [128 x 128] -> hi/lo bf16 ----
#pragma unroll 4
    for (int jj = 0; jj < 16; jj++) {
        int lin = tid + jj * 256;
        int r = lin >> 5, c = (lin & 31) * 4;
        float4 v = make_float4(0.f, 0.f, 0.f, 0.f);
        if (row0 + r < Mtot) v = *(const float4*)&A[(row0 + r) * 128 + c];
        __nv_bfloat16 h0, l0, h1, l1, h2, l2, h3, l3;
        bf16split(v.x, h0, l0); bf16split(v.y, h1, l1);
        bf16split(v.z, h2, l2); bf16split(v.w, h3, l3);
        int o = r * 136 + c;
        sb[G_AHI + o] = h0; sb[G_AHI + o + 1] = h1; sb[G_AHI + o + 2] = h2; sb[G_AHI + o + 3] = h3;
        sb[G_ALO + o] = l0; sb[G_ALO + o + 1] = l1; sb[G_ALO + o + 2] = l2; sb[G_ALO + o + 3] = l3;
    }
    // ---- stage W [64 x 128] -> hi/lo bf16 ----
#pragma unroll 4
    for (int jj = 0; jj < 8; jj++) {
        int lin = tid + jj * 256;
        int r = lin >> 5, c = (lin & 31) * 4;
        float4 v = *(const float4*)&W[(size_t)(col0 + r) * 128 + c];
        __nv_bfloat16 h0, l0, h1, l1, h2, l2, h3, l3;
        bf16split(v.x, h0, l0); bf16split(v.y, h1, l1);
        bf16split(v.z, h2, l2); bf16split(v.w, h3, l3);
        int o = r * 136 + c;
        sb[G_WHI + o] = h0; sb[G_WHI + o + 1] = h1; sb[G_WHI + o + 2] = h2; sb[G_WHI + o + 3] = h3;
        sb[G_WLO + o] = l0; sb[G_WLO + o + 1] = l1; sb[G_WLO + o + 2] = l2; sb[G_WLO + o + 3] = l3;
    }
    __syncthreads();

    float acc[2][4][4];
#pragma unroll
    for (int mt = 0; mt < 2; mt++)
#pragma unroll
        for (int nt = 0; nt < 4; nt++)
#pragma unroll
            for (int i = 0; i < 4; i++) acc[mt][nt][i] = 0.f;

    const int a_row = wm * 32 + (lane & 15);
    const int a_colsel = (lane >> 4) * 8;
    const int b_i   = lane >> 3;
    const int b_row = wn * 32 + (b_i >> 1) * 8 + (lane & 7);
    const int b_colsel = (b_i & 1) * 8;

#pragma unroll 1
    for (int ks = 0; ks < 8; ks++) {
        const int kbase = ks * 16;
        uint32_t ah[2][4], al[2][4];
#pragma unroll
        for (int mt = 0; mt < 2; mt++) {
            uint32_t off = (uint32_t)((a_row + mt * 16) * 136 + kbase + a_colsel) * 2;
            LDSM_X4(ah[mt][0], ah[mt][1], ah[mt][2], ah[mt][3], sbase + G_AHI * 2 + off);
            LDSM_X4(al[mt][0], al[mt][1], al[mt][2], al[mt][3], sbase + G_ALO * 2 + off);
        }
        uint32_t bh[4][2], bl[4][2];
#pragma unroll
        for (int np = 0; np < 2; np++) {
            uint32_t off = (uint32_t)((b_row + np * 16) * 136 + kbase + b_colsel) * 2;
            uint32_t r0, r1, r2, r3;
            LDSM_X4(r0, r1, r2, r3, sbase + G_WHI * 2 + off);
            bh[np * 2][0] = r0; bh[np * 2][1] = r1; bh[np * 2 + 1][0] = r2; bh[np * 2 + 1][1] = r3;
            LDSM_X4(r0, r1, r2, r3, sbase + G_WLO * 2 + off);
            bl[np * 2][0] = r0; bl[np * 2][1] = r1; bl[np * 2 + 1][0] = r2; bl[np * 2 + 1][1] = r3;
        }
#pragma unroll
        for (int mt = 0; mt < 2; mt++)
#pragma unroll
            for (int nt = 0; nt < 4; nt++) {
                MMA_BF16(acc[mt][nt], ah[mt], bh[nt][0], bh[nt][1]);
                MMA_BF16(acc[mt][nt], al[mt], bh[nt][0], bh[nt][1]);
                MMA_BF16(acc[mt][nt], ah[mt], bl[nt][0], bl[nt][1]);
            }
    }

    const int er = lane >> 2;
    const int ec = (lane & 3) * 2;
#pragma unroll
    for (int mt = 0; mt < 2; mt++) {
        long r = row0 + wm * 32 + mt * 16 + er;
#pragma unroll
        for (int nt = 0; nt < 4; nt++) {
            int c = col0 + wn * 32 + nt * 8 + ec;
            float b0 = bias[c], b1 = bias[c + 1];
            if (r < Mtot)
                *(float2*)&Out[r * Nout + c] =
                    make_float2(acc[mt][nt][0] + b0, acc[mt][nt][1] + b1);
            if (r + 8 < Mtot)
                *(float2*)&Out[(r + 8) * Nout + c] =
                    make_float2(acc[mt][nt][2] + b0, acc[mt][nt][3] + b1);
        }
    }
}

// ======================= comb = bias_table[rel_idx] + mask =======================
__global__ void comb_kernel(const float* __restrict__ mask,
                            const float* __restrict__ bias_table,
                            const int*   __restrict__ rel_idx)
{
    int idx = blockIdx.x * blockDim.x + threadIdx.x;
    const int total = NWIN * HEADS * N_TOK * N_TOK;
    if (idx >= total) return;
    int w   = idx / (HEADS * N_TOK * N_TOK);
    int rem = idx - w * (HEADS * N_TOK * N_TOK);
    int h   = rem / (N_TOK * N_TOK);
    int nm  = rem - h * (N_TOK * N_TOK);
    g_comb[idx] = bias_table[rel_idx[nm] * HEADS + h] + mask[w * (N_TOK * N_TOK) + nm];
}

// ======================= attention (scalar, g_qkv -> g_o) =======================
#define AQ  0
#define AK  12544
#define AV_ 25216
#define AP  37888
#define ASM_FLOATS 50688

static __device__ __forceinline__ float warp_max(float v) {
#pragma unroll
    for (int o = 16; o > 0; o >>= 1) v = fmaxf(v, __shfl_xor_sync(0xffffffffu, v, o));
    return v;
}
static __device__ __forceinline__ float warp_sum(float v) {
#pragma unroll
    for (int o = 16; o > 0; o >>= 1) v += __shfl_xor_sync(0xffffffffu, v, o);
    return v;
}

__global__ __launch_bounds__(512, 1)
void attn_kernel()
{
    extern __shared__ float sm[];
    const int b    = blockIdx.x;
    const int tid  = threadIdx.x;
    const int lane = tid & 31;
    const int warp = tid >> 5;
    const int win  = b & (NWIN - 1);

    {
        const float* qk = g_qkv + (size_t)b * N_TOK * 384;
        for (int i = tid; i < N_TOK * 32; i += 512) {
            int m = i >> 5, c4 = i & 31;
            const float4* src = (const float4*)&qk[m * 384];
            float4 q  = src[c4];
            float4 kk = src[32 + c4];
            float4 vv = src[64 + c4];
            q.x *= SCALE; q.y *= SCALE; q.z *= SCALE; q.w *= SCALE;
            *(float4*)&sm[AQ + m * 128 + c4 * 4] = q;
            int c = c4 * 4;
            sm[AK + (c + 0) * 99 + m] = kk.x;
            sm[AK + (c + 1) * 99 + m] = kk.y;
            sm[AK + (c + 2) * 99 + m] = kk.z;
            sm[AK + (c + 3) * 99 + m] = kk.w;
            sm[AV_ + (c + 0) * 99 + m] = vv.x;
            sm[AV_ + (c + 1) * 99 + m] = vv.y;
            sm[AV_ + (c + 2) * 99 + m] = vv.z;
            sm[AV_ + (c + 3) * 99 + m] = vv.w;
        }
    }
    __syncthreads();

    const float* combw = g_comb + (size_t)(win * HEADS) * N_TOK * N_TOK;

#pragma unroll 1
    for (int ph = 0; ph < 4; ph++) {
        const int base = ph * 32;
        {
            const int g  = warp >> 2;
            const int h  = warp & 3;
            const int n0 = base + g * 8;
            if (n0 < N_TOK) {
                float s[8][4];
#pragma unroll
                for (int r = 0; r < 8; r++)
#pragma unroll
                    for (int k = 0; k < 4; k++) s[r][k] = 0.f;

#pragma unroll 1
                for (int d4 = 0; d4 < 8; d4++) {
                    float4 q4[8];
#pragma unroll
                    for (int r = 0; r < 8; r++)
                        q4[r] = *(const float4*)&sm[AQ + (n0 + r) * 128 + h * 32 + d4 * 4];
#pragma unroll
                    for (int dd = 0; dd < 4; dd++) {
                        int d = d4 * 4 + dd;
                        float kv[4];
#pragma unroll
                        for (int k = 0; k < 4; k++)
                            kv[k] = sm[AK + (h * 32 + d) * 99 + lane + 32 * k];
#pragma unroll
                        for (int r = 0; r < 8; r++) {
                            float qv = (dd == 0) ? q4[r].x : (dd == 1) ? q4[r].y
                                     : (dd == 2) ? q4[r].z : q4[r].w;
#pragma unroll
                            for (int k = 0; k < 4; k++) s[r][k] = fmaf(qv, kv[k], s[r][k]);
                        }
                    }
                }
#pragma unroll 1
                for (int r = 0; r < 8; r++) {
                    const int n = n0 + r;
                    if (n >= N_TOK) break;
                    const float* cp = combw + ((size_t)h * N_TOK + n) * N_TOK;
                    float l[4];
#pragma unroll
                    for (int k = 0; k < 4; k++) {
                        int m = lane + 32 * k;
                        l[k] = (m < N_TOK) ? (s[r][k] + cp[m]) : -1e30f;
                    }
                    float mx = warp_max(fmaxf(fmaxf(l[0], l[1]), fmaxf(l[2], l[3])));
                    float e[4], sum = 0.f;
#pragma unroll
                    for (int k = 0; k < 4; k++) { e[k] = __expf(l[k] - mx); sum += e[k]; }
                    sum = warp_sum(sum);
                    float inv = __fdividef(1.0f, sum);
#pragma unroll
                    for (int k = 0; k < 4; k++) {
                        int m = lane + 32 * k;
                        if (m < N_TOK)
                            sm[AP + h * 3200 + (n - base) * 100 + m] = e[k] * inv;
                    }
                }
            }
        }
        __syncthreads();

        {
            const int g  = warp >> 2;
            const int h  = warp & 3;
            const int n0 = base + g * 8;
            if (n0 < N_TOK) {
                const int c = h * 32 + lane;
                const float* vb = &sm[AV_ + c * 99];
                const float* pb = &sm[AP + h * 3200 + (n0 - base) * 100];
                float acc[8];
#pragma unroll
                for (int r = 0; r < 8; r++) acc[r] = 0.f;
#pragma unroll 4
                for (int mc = 0; mc < 24; mc++) {
                    float v0 = vb[4 * mc + 0], v1 = vb[4 * mc + 1];
                    float v2 = vb[4 * mc + 2], v3 = vb[4 * mc + 3];
#pragma unroll
                    for (int r = 0; r < 8; r++) {
                        float4 p = *(const float4*)&pb[r * 100 + 4 * mc];
                        acc[r] = fmaf(p.x, v0, acc[r]);
                        acc[r] = fmaf(p.y, v1, acc[r]);
                        acc[r] = fmaf(p.z, v2, acc[r]);
                        acc[r] = fmaf(p.w, v3, acc[r]);
                    }
                }
                float v96 = vb[96], v97 = vb[97];
#pragma unroll
                for (int r = 0; r < 8; r++) {
                    acc[r] = fmaf(pb[r * 100 + 96], v96, acc[r]);
                    acc[r] = fmaf(pb[r * 100 + 97], v97, acc[r]);
                    int n = n0 + r;
                    if (n < N_TOK)
                        g_o[((size_t)b * N_TOK + n) * 128 + c] = acc[r];
                }
            }
        }
        __syncthreads();
    }
}

// ======================= launch =======================
extern "C" void kernel_launch(void* const* d_in, const int* in_sizes, int n_in,
                              void* d_out, int out_size)
{
    const float* x          = (const float*)d_in[0];
    const float* mask       = (const float*)d_in[1];
    const float* qkv_w      = (const float*)d_in[2];
    const float* qkv_b      = (const float*)d_in[3];
    const float* proj_w     = (const float*)d_in[4];
    const float* proj_b     = (const float*)d_in[5];
    const float* bias_table = (const float*)d_in[6];
    const int*   rel_idx    = (const int*)d_in[7];
    float*       out        = (float*)d_out;

    const int B    = in_sizes[0] / (N_TOK * DIM);
    const int Mtot = B * N_TOK;
    const int mtiles = (Mtot + 127) / 128;

    float *qkv_ptr, *o_ptr;
    cudaGetSymbolAddress((void**)&qkv_ptr, g_qkv);
    cudaGetSymbolAddress((void**)&o_ptr, g_o);

    cudaFuncSetAttribute(gemm_bf16x3,
                         cudaFuncAttributeMaxDynamicSharedMemorySize, G_SMEM_BYTES);
    cudaFuncSetAttribute(attn_kernel,
                         cudaFuncAttributeMaxDynamicSharedMemorySize,
                         ASM_FLOATS * (int)sizeof(float));

    {
        const int total = NWIN * HEADS * N_TOK * N_TOK;
        comb_kernel<<<(total + 255) / 256, 256>>>(mask, bias_table, rel_idx);
    }
    gemm_bf16x3<<<dim3(mtiles, 6), 256, G_SMEM_BYTES>>>(x, qkv_w, qkv_b, qkv_ptr, 384, Mtot);
    attn_kernel<<<B, 512, ASM_FLOATS * sizeof(float)>>>();
    gemm_bf16x3<<<dim3(mtiles, 2), 256, G_SMEM_BYTES>>>(o_ptr, proj_w, proj_b, out, 128, Mtot);
}

// round 6
// speedup vs baseline: 3.3861x; 1.0724x over previous
#include <cuda_runtime.h>
#include <cuda_bf16.h>
#include <cstdint>

#define N_TOK 98
#define DIM   128
#define HEADS 4
#define NWIN  64
#define SCALE 0.17677669529663687f

#define MAX_B    2048
#define MAX_MTOT (MAX_B * N_TOK)

__device__ float g_qkv[(size_t)MAX_MTOT * 384];
__device__ float g_o[(size_t)MAX_MTOT * 128];
__device__ float g_comb[NWIN * HEADS * N_TOK * N_TOK];

// ======================= helpers =======================
static __device__ __forceinline__ uint32_t smem_u32(const void* p) {
    uint32_t a;
    asm("{ .reg .u64 t; cvta.to.shared.u64 t, %1; cvt.u32.u64 %0, t; }" : "=r"(a) : "l"(p));
    return a;
}
#define LDSM_X4(r0, r1, r2, r3, addr)                                          \
    asm volatile("ldmatrix.sync.aligned.m8n8.x4.shared.b16 {%0,%1,%2,%3}, [%4];" \
                 : "=r"(r0), "=r"(r1), "=r"(r2), "=r"(r3) : "r"(addr))
#define MMA_BF16(c, a, b0, b1)                                                 \
    asm volatile("mma.sync.aligned.m16n8k16.row.col.f32.bf16.bf16.f32 "        \
                 "{%0,%1,%2,%3}, {%4,%5,%6,%7}, {%8,%9}, {%0,%1,%2,%3};"       \
                 : "+f"((c)[0]), "+f"((c)[1]), "+f"((c)[2]), "+f"((c)[3])      \
                 : "r"((a)[0]), "r"((a)[1]), "r"((a)[2]), "r"((a)[3]),         \
                   "r"(b0), "r"(b1))

static __device__ __forceinline__ void bf16split(float a, __nv_bfloat16& h, __nv_bfloat16& l) {
    h = __float2bfloat16_rn(a);
    l = __float2bfloat16_rn(a - __bfloat162float(h));
}
static __device__ __forceinline__ float warp_max(float v) {
#pragma unroll
    for (int o = 16; o > 0; o >>= 1) v = fmaxf(v, __shfl_xor_sync(0xffffffffu, v, o));
    return v;
}
static __device__ __forceinline__ float warp_sum(float v) {
#pragma unroll
    for (int o = 16; o > 0; o >>= 1) v += __shfl_xor_sync(0xffffffffu, v, o);
    return v;
}

extern __shared__ char smraw[];

// ======================= bf16x3 GEMM: Out[M,N] = A[M,128] @ W[N,128]^T + bias =======================
// tile 128x128, 8 warps (wm 0..3 x wn 0..1, each 32m x 64n)
#define G_AHI 0
#define G_ALO 17408
#define G_WHI 34816
#define G_WLO 52224
#define G_SMEM_BYTES (69632 * 2)     // 139264

__global__ __launch_bounds__(256)
void gemm_bf16x3(const float* __restrict__ A,
                 const float* __restrict__ W,
                 const float* __restrict__ bias,
                 float* __restrict__ Out,
                 int Nout, int Mtot)
{
    __nv_bfloat16* sb = (__nv_bfloat16*)smraw;
    const uint32_t sbase = smem_u32(sb);
    const int tid  = threadIdx.x;
    const int lane = tid & 31;
    const int warp = tid >> 5;
    const int wm   = warp & 3;
    const int wn   = warp >> 2;
    const long row0 = (long)blockIdx.x * 128;
    const int  col0 = blockIdx.y * 128;

    // ---- stage A [128 x 128] -> hi/lo bf16 ----
#pragma unroll 4
    for (int jj = 0; jj < 16; jj++) {
        int lin = tid + jj * 256;
        int r = lin >> 5, c = (lin & 31) * 4;
        float4 v = make_float4(0.f, 0.f, 0.f, 0.f);
        if (row0 + r < Mtot) v = *(const float4*)&A[(row0 + r) * 128 + c];
        __nv_bfloat16 h0, l0, h1, l1, h2, l2, h3, l3;
        bf16split(v.x, h0, l0); bf16split(v.y, h1, l1);
        bf16split(v.z, h2, l2); bf16split(v.w, h3, l3);
        int o = r * 136 + c;
        sb[G_AHI + o] = h0; sb[G_AHI + o + 1] = h1; sb[G_AHI + o + 2] = h2; sb[G_AHI + o + 3] = h3;
        sb[G_ALO + o] = l0; sb[G_ALO + o + 1] = l1; sb[G_ALO + o + 2] = l2; sb[G_ALO + o + 3] = l3;
    }
    // ---- stage W [128 x 128] -> hi/lo bf16 ----
#pragma unroll 4
    for (int jj = 0; jj < 16; jj++) {
        int lin = tid + jj * 256;
        int r = lin >> 5, c = (lin & 31) * 4;
        float4 v = *(const float4*)&W[(size_t)(col0 + r) * 128 + c];
        __nv_bfloat16 h0, l0, h1, l1, h2, l2, h3, l3;
        bf16split(v.x, h0, l0); bf16split(v.y, h1, l1);
        bf16split(v.z, h2, l2); bf16split(v.w, h3, l3);
        int o = r * 136 + c;
        sb[G_WHI + o] = h0; sb[G_WHI + o + 1] = h1; sb[G_WHI + o + 2] = h2; sb[G_WHI + o + 3] = h3;
        sb[G_WLO + o] = l0; sb[G_WLO + o + 1] = l1; sb[G_WLO + o + 2] = l2; sb[G_WLO + o + 3] = l3;
    }
    __syncthreads();

    float acc[2][8][4];
#pragma unroll
    for (int mt = 0; mt < 2; mt++)
#pragma unroll
        for (int nt = 0; nt < 8; nt++)
#pragma unroll
            for (int i = 0; i < 4; i++) acc[mt][nt][i] = 0.f;

    const int a_row = wm * 32 + (lane & 15);
    const int a_colsel = (lane >> 4) * 8;
    const int b_i   = lane >> 3;
    const int b_rp  = (b_i >> 1) * 8 + (lane & 7);
    const int b_colsel = (b_i & 1) * 8;

#pragma unroll 1
    for (int ks = 0; ks < 8; ks++) {
        const int kbase = ks * 16;
        uint32_t ah[2][4], al[2][4];
#pragma unroll
        for (int mt = 0; mt < 2; mt++) {
            uint32_t off = (uint32_t)((a_row + mt * 16) * 136 + kbase + a_colsel) * 2;
            LDSM_X4(ah[mt][0], ah[mt][1], ah[mt][2], ah[mt][3], sbase + G_AHI * 2 + off);
            LDSM_X4(al[mt][0], al[mt][1], al[mt][2], al[mt][3], sbase + G_ALO * 2 + off);
        }
        uint32_t bh[8][2], bl[8][2];
#pragma unroll
        for (int np = 0; np < 4; np++) {
            uint32_t off = (uint32_t)((wn * 64 + np * 16 + b_rp) * 136 + kbase + b_colsel) * 2;
            uint32_t r0, r1, r2, r3;
            LDSM_X4(r0, r1, r2, r3, sbase + G_WHI * 2 + off);
            bh[np * 2][0] = r0; bh[np * 2][1] = r1; bh[np * 2 + 1][0] = r2; bh[np * 2 + 1][1] = r3;
            LDSM_X4(r0, r1, r2, r3, sbase + G_WLO * 2 + off);
            bl[np * 2][0] = r0; bl[np * 2][1] = r1; bl[np * 2 + 1][0] = r2; bl[np * 2 + 1][1] = r3;
        }
#pragma unroll
        for (int mt = 0; mt < 2; mt++)
#pragma unroll
            for (int nt = 0; nt < 8; nt++) {
                MMA_BF16(acc[mt][nt], ah[mt], bh[nt][0], bh[nt][1]);
                MMA_BF16(acc[mt][nt], al[mt], bh[nt][0], bh[nt][1]);
                MMA_BF16(acc[mt][nt], ah[mt], bl[nt][0], bl[nt][1]);
            }
    }

    const int er = lane >> 2;
    const int ec = (lane & 3) * 2;
#pragma unroll
    for (int mt = 0; mt < 2; mt++) {
        long r = row0 + wm * 32 + mt * 16 + er;
#pragma unroll
        for (int nt = 0; nt < 8; nt++) {
            int c = col0 + wn * 64 + nt * 8 + ec;
            float b0 = bias[c], b1 = bias[c + 1];
            if (r < Mtot)
                *(float2*)&Out[r * Nout + c] =
                    make_float2(acc[mt][nt][0] + b0, acc[mt][nt][1] + b1);
            if (r + 8 < Mtot)
                *(float2*)&Out[(r + 8) * Nout + c] =
                    make_float2(acc[mt][nt][2] + b0, acc[mt][nt][3] + b1);
        }
    }
}

// ======================= comb = bias_table[rel_idx] + mask =======================
__global__ void comb_kernel(const float* __restrict__ mask,
                            const float* __restrict__ bias_table,
                            const int*   __restrict__ rel_idx)
{
    int idx = blockIdx.x * blockDim.x + threadIdx.x;
    const int total = NWIN * HEADS * N_TOK * N_TOK;
    if (idx >= total) return;
    int w   = idx / (HEADS * N_TOK * N_TOK);
    int rem = idx - w * (HEADS * N_TOK * N_TOK);
    int h   = rem / (N_TOK * N_TOK);
    int nm  = rem - h * (N_TOK * N_TOK);
    g_comb[idx] = bias_table[rel_idx[nm] * HEADS + h] + mask[w * (N_TOK * N_TOK) + nm];
}

// ======================= attention v2: tensor-core QK^T and PV =======================
// per-head smem byte offsets
#define SQH 0          // Q hi [112][40] bf16
#define SQL 8960
#define SKH 17920      // K hi [112][40]
#define SKL 26880
#define SVH 35840      // V^T hi [40 ch][120 key]
#define SVL 45440
#define SS  55040      // scores fp32 [112][116]
#define SPH 107008     // P hi [112][120] bf16
#define SPL 133888
#define ATTN_SMEM 160768

__global__ __launch_bounds__(512, 1)
void attn_kernel()
{
    char* sb = smraw;
    const uint32_t sbase = smem_u32(sb);
    const int b    = blockIdx.x;
    const int tid  = threadIdx.x;
    const int lane = tid & 31;
    const int warp = tid >> 5;
    const int win  = b & (NWIN - 1);

    // ---- one-time zero padding ----
    // Q/K pad rows 98..111 (4 contiguous bufs of 8960B, pad = last 1120B each)
    for (int i = tid; i < 1120; i += 512) {
        int buf = i / 280, w = i - buf * 280;
        *(uint32_t*)(sb + buf * 8960 + 7840 + w * 4) = 0u;
    }
    // V^T pad keys 98..119 for 40 channel rows, both bufs
    for (int i = tid; i < 1760; i += 512) {
        int buf = i / 880, j = i - buf * 880;
        int r = j / 22, k = 98 + (j - r * 22);
        *(unsigned short*)(sb + SVH + buf * 9600 + (r * 120 + k) * 2) = 0;
    }
    // P pad rows 98..111 (contiguous 3360B per buf)
    for (int i = tid; i < 1680; i += 512) {
        int buf = i / 840, w = i - buf * 840;
        *(uint32_t*)(sb + SPH + buf * 26880 + 23520 + w * 4) = 0u;
    }

    const int mt_s = warp >> 1;          // score/PV m-tile
    const int half = warp & 1;
    const int a_rp = lane & 15;
    const int a_cs = (lane >> 4) * 8;
    const int b_i  = lane >> 3;
    const int b_rp = (b_i >> 1) * 8 + (lane & 7);
    const int b_cs = (b_i & 1) * 8;
    const int er   = lane >> 2;
    const int ec   = (lane & 3) * 2;

#pragma unroll 1
    for (int h = 0; h < HEADS; h++) {
        __syncthreads();
        // ---- stage Qh/Kh (row-major [tok][ch]) and Vh^T ([ch][tok]), bf16 hi/lo ----
        {
            const float* qk = g_qkv + (size_t)b * N_TOK * 384 + h * 32;
            for (int i = tid; i < N_TOK * 8; i += 512) {
                int m = i >> 3, c = (i & 7) * 4;
                const float* rp = qk + m * 384 + c;
                float4 q = *(const float4*)rp;
                float4 k = *(const float4*)(rp + 128);
                float4 v = *(const float4*)(rp + 256);
                q.x *= SCALE; q.y *= SCALE; q.z *= SCALE; q.w *= SCALE;
                __nv_bfloat16 hh[4], ll[4];
                bf16split(q.x, hh[0], ll[0]); bf16split(q.y, hh[1], ll[1]);
                bf16split(q.z, hh[2], ll[2]); bf16split(q.w, hh[3], ll[3]);
                *(uint2*)(sb + SQH + (m * 40 + c) * 2) = *(uint2*)hh;
                *(uint2*)(sb + SQL + (m * 40 + c) * 2) = *(uint2*)ll;
                bf16split(k.x, hh[0], ll[0]); bf16split(k.y, hh[1], ll[1]);
                bf16split(k.z, hh[2], ll[2]); bf16split(k.w, hh[3], ll[3]);
                *(uint2*)(sb + SKH + (m * 40 + c) * 2) = *(uint2*)hh;
                *(uint2*)(sb + SKL + (m * 40 + c) * 2) = *(uint2*)ll;
                float vf[4] = {v.x, v.y, v.z, v.w};
#pragma unroll
                for (int j = 0; j < 4; j++) {
                    __nv_bfloat16 vh, vl;
                    bf16split(vf[j], vh, vl);
                    *(__nv_bfloat16*)(sb + SVH + ((c + j) * 120 + m) * 2) = vh;
                    *(__nv_bfloat16*)(sb + SVL + ((c + j) * 120 + m) * 2) = vl;
                }
            }
        }
        __syncthreads();

        // ---- scores: warp item = (mt 0..6, half 0..1) ----
        if (warp < 14) {
            const int ntiles  = half ? 6 : 8;
            const int keybase = half * 64;
            float acc[8][4];
#pragma unroll
            for (int nt = 0; nt < 8; nt++)
#pragma unroll
                for (int i = 0; i < 4; i++) acc[nt][i] = 0.f;

#pragma unroll
            for (int ks = 0; ks < 2; ks++) {
                const int kb = ks * 16;
                uint32_t ah[4], al[4];
                uint32_t aoff = (uint32_t)((mt_s * 16 + a_rp) * 40 + kb + a_cs) * 2;
                LDSM_X4(ah[0], ah[1], ah[2], ah[3], sbase + SQH + aoff);
                LDSM_X4(al[0], al[1], al[2], al[3], sbase + SQL + aoff);
                uint32_t bh[8][2], bl[8][2];
#pragma unroll
                for (int np = 0; np < 4; np++) {
                    if (np * 2 >= ntiles) break;
                    uint32_t boff = (uint32_t)((keybase + np * 16 + b_rp) * 40 + kb + b_cs) * 2;
                    uint32_t r0, r1, r2, r3;
                    LDSM_X4(r0, r1, r2, r3, sbase + SKH + boff);
                    bh[np * 2][0] = r0; bh[np * 2][1] = r1; bh[np * 2 + 1][0] = r2; bh[np * 2 + 1][1] = r3;
                    LDSM_X4(r0, r1, r2, r3, sbase + SKL + boff);
                    bl[np * 2][0] = r0; bl[np * 2][1] = r1; bl[np * 2 + 1][0] = r2; bl[np * 2 + 1][1] = r3;
                }
#pragma unroll
                for (int nt = 0; nt < 8; nt++) {
                    if (nt >= ntiles) break;
                    MMA_BF16(acc[nt], ah, bh[nt][0], bh[nt][1]);
                    MMA_BF16(acc[nt], al, bh[nt][0], bh[nt][1]);
                    MMA_BF16(acc[nt], ah, bl[nt][0], bl[nt][1]);
                }
            }
            // write raw scores to S
#pragma unroll
            for (int nt = 0; nt < 8; nt++) {
                if (nt >= ntiles) break;
                int col = keybase + nt * 8 + ec;
                int row = mt_s * 16 + er;
                *(float2*)(sb + SS + (row * 116 + col) * 4) = make_float2(acc[nt][0], acc[nt][1]);
                *(float2*)(sb + SS + ((row + 8) * 116 + col) * 4) = make_float2(acc[nt][2], acc[nt][3]);
            }
        }
        __syncthreads();

        // ---- softmax: S + comb -> P (bf16 hi/lo), zero-pad keys 98..119 ----
        {
            const float* combh = g_comb + ((size_t)(win * HEADS + h) * N_TOK) * N_TOK;
            for (int n = warp; n < N_TOK; n += 16) {
                float l[4];
#pragma unroll
                for (int j = 0; j < 4; j++) {
                    int m = lane + 32 * j;
                    l[j] = (m < N_TOK)
                         ? *(float*)(sb + SS + (n * 116 + m) * 4) + combh[n * N_TOK + m]
                         : -1e30f;
                }
                float mx = warp_max(fmaxf(fmaxf(l[0], l[1]), fmaxf(l[2], l[3])));
                float e[4], sum = 0.f;
#pragma unroll
                for (int j = 0; j < 4; j++) { e[j] = __expf(l[j] - mx); sum += e[j]; }
                sum = warp_sum(sum);
                float inv = __fdividef(1.0f, sum);
#pragma unroll
                for (int j = 0; j < 4; j++) {
                    int m = lane + 32 * j;
                    if (m < N_TOK) {
                        __nv_bfloat16 ph, pl;
                        bf16split(e[j] * inv, ph, pl);
                        *(__nv_bfloat16*)(sb + SPH + (n * 120 + m) * 2) = ph;
                        *(__nv_bfloat16*)(sb + SPL + (n * 120 + m) * 2) = pl;
                    } else if (m < 120) {
                        *(unsigned short*)(sb + SPH + (n * 120 + m) * 2) = 0;
                        *(unsigned short*)(sb + SPL + (n * 120 + m) * 2) = 0;
                    }
                }
            }
        }
        __syncthreads();

        // ---- PV: warp item = (mt 0..6, cp 0..1); 16 channels each ----
        if (warp < 14) {
            const int cp = half;
            float acc[2][4];
#pragma unroll
            for (int nt = 0; nt < 2; nt++)
#pragma unroll
                for (int i = 0; i < 4; i++) acc[nt][i] = 0.f;

#pragma unroll 1
            for (int ks = 0; ks < 7; ks++) {
                const int kb = ks * 16;
                uint32_t ah[4], al[4];
                uint32_t aoff = (uint32_t)((mt_s * 16 + a_rp) * 120 + kb + a_cs) * 2;
                LDSM_X4(ah[0], ah[1], ah[2], ah[3], sbase + SPH + aoff);
                LDSM_X4(al[0], al[1], al[2], al[3], sbase + SPL + aoff);
                uint32_t boff = (uint32_t)((cp * 16 + b_rp) * 120 + kb + b_cs) * 2;
                uint32_t bh0, bh1, bh2, bh3, bl0, bl1, bl2, bl3;
                LDSM_X4(bh0, bh1, bh2, bh3, sbase + SVH + boff);
                LDSM_X4(bl0, bl1, bl2, bl3, sbase + SVL + boff);
                MMA_BF16(acc[0], ah, bh0, bh1);
                MMA_BF16(acc[0], al, bh0, bh1);
                MMA_BF16(acc[0], ah, bl0, bl1);
                MMA_BF16(acc[1], ah, bh2, bh3);
                MMA_BF16(acc[1], al, bh2, bh3);
                MMA_BF16(acc[1], ah, bl2, bl3);
            }
#pragma unroll
            for (int nt = 0; nt < 2; nt++) {
                int ch  = h * 32 + cp * 16 + nt * 8 + ec;
                int row = mt_s * 16 + er;
                if (row < N_TOK)
                    *(float2*)&g_o[((size_t)b * N_TOK + row) * 128 + ch] =
                        make_float2(acc[nt][0], acc[nt][1]);
                if (row + 8 < N_TOK)
                    *(float2*)&g_o[((size_t)b * N_TOK + row + 8) * 128 + ch] =
                        make_float2(acc[nt][2], acc[nt][3]);
            }
        }
    }
}

// ======================= launch =======================
extern "C" void kernel_launch(void* const* d_in, const int* in_sizes, int n_in,
                              void* d_out, int out_size)
{
    const float* x          = (const float*)d_in[0];
    const float* mask       = (const float*)d_in[1];
    const float* qkv_w      = (const float*)d_in[2];
    const float* qkv_b      = (const float*)d_in[3];
    const float* proj_w     = (const float*)d_in[4];
    const float* proj_b     = (const float*)d_in[5];
    const float* bias_table = (const float*)d_in[6];
    const int*   rel_idx    = (const int*)d_in[7];
    float*       out        = (float*)d_out;

    const int B    = in_sizes[0] / (N_TOK * DIM);
    const int Mtot = B * N_TOK;
    const int mtiles = (Mtot + 127) / 128;

    float *qkv_ptr, *o_ptr;
    cudaGetSymbolAddress((void**)&qkv_ptr, g_qkv);
    cudaGetSymbolAddress((void**)&o_ptr, g_o);

    cudaFuncSetAttribute(gemm_bf16x3,
                         cudaFuncAttributeMaxDynamicSharedMemorySize, G_SMEM_BYTES);
    cudaFuncSetAttribute(attn_kernel,
                         cudaFuncAttributeMaxDynamicSharedMemorySize, ATTN_SMEM);

    {
        const int total = NWIN * HEADS * N_TOK * N_TOK;
        comb_kernel<<<(total + 255) / 256, 256>>>(mask, bias_table, rel_idx);
    }
    gemm_bf16x3<<<dim3(mtiles, 3), 256, G_SMEM_BYTES>>>(x, qkv_w, qkv_b, qkv_ptr, 384, Mtot);
    attn_kernel<<<B, 512, ATTN_SMEM>>>();
    gemm_bf16x3<<<dim3(mtiles, 1), 256, G_SMEM_BYTES>>>(o_ptr, proj_w, proj_b, out, 128, Mtot);
}

// round 7
// speedup vs baseline: 4.3299x; 1.2787x over previous
#include <cuda_runtime.h>
#include <cuda_bf16.h>
#include <cstdint>

#define N_TOK 98
#define DIM   128
#define HEADS 4
#define NWIN  64
#define SCALE 0.17677669529663687f

#define MAX_B    2048
#define MAX_MTOT (MAX_B * N_TOK)

__device__ float g_qkv[(size_t)MAX_MTOT * 384];
__device__ float g_o[(size_t)MAX_MTOT * 128];
__device__ float g_comb[NWIN * HEADS * N_TOK * N_TOK];

// ======================= helpers =======================
static __device__ __forceinline__ uint32_t smem_u32(const void* p) {
    uint32_t a;
    asm("{ .reg .u64 t; cvta.to.shared.u64 t, %1; cvt.u32.u64 %0, t; }" : "=r"(a) : "l"(p));
    return a;
}
#define LDSM_X4(r0, r1, r2, r3, addr)                                          \
    asm volatile("ldmatrix.sync.aligned.m8n8.x4.shared.b16 {%0,%1,%2,%3}, [%4];" \
                 : "=r"(r0), "=r"(r1), "=r"(r2), "=r"(r3) : "r"(addr))
#define MMA_BF16(c, a, b0, b1)                                                 \
    asm volatile("mma.sync.aligned.m16n8k16.row.col.f32.bf16.bf16.f32 "        \
                 "{%0,%1,%2,%3}, {%4,%5,%6,%7}, {%8,%9}, {%0,%1,%2,%3};"       \
                 : "+f"((c)[0]), "+f"((c)[1]), "+f"((c)[2]), "+f"((c)[3])      \
                 : "r"((a)[0]), "r"((a)[1]), "r"((a)[2]), "r"((a)[3]),         \
                   "r"(b0), "r"(b1))

static __device__ __forceinline__ void bf16split(float a, __nv_bfloat16& h, __nv_bfloat16& l) {
    h = __float2bfloat16_rn(a);
    l = __float2bfloat16_rn(a - __bfloat162float(h));
}
// pack two fp32 into bf16x2 hi parts (return) and lo parts (out-param); a -> low half
static __device__ __forceinline__ uint32_t pack_split(float a, float b, uint32_t& lo) {
    __nv_bfloat16 ah, al, bh, bl;
    bf16split(a, ah, al); bf16split(b, bh, bl);
    uint16_t ahu = *(uint16_t*)&ah, alu = *(uint16_t*)&al;
    uint16_t bhu = *(uint16_t*)&bh, blu = *(uint16_t*)&bl;
    lo = ((uint32_t)blu << 16) | alu;
    return ((uint32_t)bhu << 16) | ahu;
}

extern __shared__ char smraw[];

// ======================= bf16x3 GEMM: Out[M,N] = A[M,128] @ W[N,128]^T + bias =======================
// tile 128x128, 8 warps; A staged full-K (stride 136), W staged in two K-64 chunks (stride 72)
#define G_AHI 0
#define G_ALO 34816
#define G_WHI 69632
#define G_WLO 88064
#define G_SMEM_BYTES 106496

__global__ __launch_bounds__(256)
void gemm_bf16x3(const float* __restrict__ A,
                 const float* __restrict__ W,
                 const float* __restrict__ bias,
                 float* __restrict__ Out,
                 int Nout, int Mtot)
{
    __nv_bfloat16* sb = (__nv_bfloat16*)smraw;
    const uint32_t sbase = smem_u32(sb);
    const int tid  = threadIdx.x;
    const int lane = tid & 31;
    const int warp = tid >> 5;
    const int wm   = warp & 3;
    const int wn   = warp >> 2;
    const long row0 = (long)blockIdx.x * 128;
    const int  col0 = blockIdx.y * 128;

    // ---- stage A [128 x 128] -> hi/lo bf16, stride 136 ----
#pragma unroll 4
    for (int jj = 0; jj < 16; jj++) {
        int lin = tid + jj * 256;
        int r = lin >> 5, c = (lin & 31) * 4;
        float4 v = make_float4(0.f, 0.f, 0.f, 0.f);
        if (row0 + r < Mtot) v = *(const float4*)&A[(row0 + r) * 128 + c];
        __nv_bfloat16 h0, l0, h1, l1, h2, l2, h3, l3;
        bf16split(v.x, h0, l0); bf16split(v.y, h1, l1);
        bf16split(v.z, h2, l2); bf16split(v.w, h3, l3);
        int o = r * 136 + c;
        sb[(G_AHI>>1) + o] = h0; sb[(G_AHI>>1) + o + 1] = h1; sb[(G_AHI>>1) + o + 2] = h2; sb[(G_AHI>>1) + o + 3] = h3;
        sb[(G_ALO>>1) + o] = l0; sb[(G_ALO>>1) + o + 1] = l1; sb[(G_ALO>>1) + o + 2] = l2; sb[(G_ALO>>1) + o + 3] = l3;
    }

    float acc[2][8][4];
#pragma unroll
    for (int mt = 0; mt < 2; mt++)
#pragma unroll
        for (int nt = 0; nt < 8; nt++)
#pragma unroll
            for (int i = 0; i < 4; i++) acc[mt][nt][i] = 0.f;

    const int a_row = wm * 32 + (lane & 15);
    const int a_cs  = (lane >> 4) * 8;
    const int b_i   = lane >> 3;
    const int b_rp  = (b_i >> 1) * 8 + (lane & 7);
    const int b_cs  = (b_i & 1) * 8;

#pragma unroll 1
    for (int kc = 0; kc < 2; kc++) {
        __syncthreads();
        // ---- stage W chunk [128 rows x 64 K] -> hi/lo, stride 72 ----
#pragma unroll
        for (int jj = 0; jj < 8; jj++) {
            int lin = tid + jj * 256;
            int r = lin >> 4, c = (lin & 15) * 4;
            float4 v = *(const float4*)&W[(size_t)(col0 + r) * 128 + kc * 64 + c];
            __nv_bfloat16 h0, l0, h1, l1, h2, l2, h3, l3;
            bf16split(v.x, h0, l0); bf16split(v.y, h1, l1);
            bf16split(v.z, h2, l2); bf16split(v.w, h3, l3);
            int o = r * 72 + c;
            sb[(G_WHI>>1) + o] = h0; sb[(G_WHI>>1) + o + 1] = h1; sb[(G_WHI>>1) + o + 2] = h2; sb[(G_WHI>>1) + o + 3] = h3;
            sb[(G_WLO>>1) + o] = l0; sb[(G_WLO>>1) + o + 1] = l1; sb[(G_WLO>>1) + o + 2] = l2; sb[(G_WLO>>1) + o + 3] = l3;
        }
        __syncthreads();

#pragma unroll
        for (int ks = 0; ks < 4; ks++) {
            uint32_t ah[2][4], al[2][4];
#pragma unroll
            for (int mt = 0; mt < 2; mt++) {
                uint32_t off = (uint32_t)((a_row + mt * 16) * 136 + kc * 64 + ks * 16 + a_cs) * 2;
                LDSM_X4(ah[mt][0], ah[mt][1], ah[mt][2], ah[mt][3], sbase + G_AHI + off);
                LDSM_X4(al[mt][0], al[mt][1], al[mt][2], al[mt][3], sbase + G_ALO + off);
            }
#pragma unroll
            for (int np = 0; np < 4; np++) {
                uint32_t off = (uint32_t)((wn * 64 + np * 16 + b_rp) * 72 + ks * 16 + b_cs) * 2;
                uint32_t h0, h1, h2, h3, l0, l1, l2, l3;
                LDSM_X4(h0, h1, h2, h3, sbase + G_WHI + off);
                LDSM_X4(l0, l1, l2, l3, sbase + G_WLO + off);
#pragma unroll
                for (int mt = 0; mt < 2; mt++) {
                    MMA_BF16(acc[mt][np * 2],     ah[mt], h0, h1);
                    MMA_BF16(acc[mt][np * 2],     al[mt], h0, h1);
                    MMA_BF16(acc[mt][np * 2],     ah[mt], l0, l1);
                    MMA_BF16(acc[mt][np * 2 + 1], ah[mt], h2, h3);
                    MMA_BF16(acc[mt][np * 2 + 1], al[mt], h2, h3);
                    MMA_BF16(acc[mt][np * 2 + 1], ah[mt], l2, l3);
                }
            }
        }
    }

    const int er = lane >> 2;
    const int ec = (lane & 3) * 2;
#pragma unroll
    for (int mt = 0; mt < 2; mt++) {
        long r = row0 + wm * 32 + mt * 16 + er;
#pragma unroll
        for (int nt = 0; nt < 8; nt++) {
            int c = col0 + wn * 64 + nt * 8 + ec;
            float b0 = bias[c], b1 = bias[c + 1];
            if (r < Mtot)
                *(float2*)&Out[r * Nout + c] =
                    make_float2(acc[mt][nt][0] + b0, acc[mt][nt][1] + b1);
            if (r + 8 < Mtot)
                *(float2*)&Out[(r + 8) * Nout + c] =
                    make_float2(acc[mt][nt][2] + b0, acc[mt][nt][3] + b1);
        }
    }
}

// ======================= comb = bias_table[rel_idx] + mask =======================
__global__ void comb_kernel(const float* __restrict__ mask,
                            const float* __restrict__ bias_table,
                            const int*   __restrict__ rel_idx)
{
    int idx = blockIdx.x * blockDim.x + threadIdx.x;
    const int total = NWIN * HEADS * N_TOK * N_TOK;
    if (idx >= total) return;
    int w   = idx / (HEADS * N_TOK * N_TOK);
    int rem = idx - w * (HEADS * N_TOK * N_TOK);
    int h   = rem / (N_TOK * N_TOK);
    int nm  = rem - h * (N_TOK * N_TOK);
    g_comb[idx] = bias_table[rel_idx[nm] * HEADS + h] + mask[w * (N_TOK * N_TOK) + nm];
}

// ======================= attention v3: register-resident flash =======================
// smem byte offsets (all bf16 arrays)
#define TQH 0          // Q hi [112 tok][136 ch]   (rows 98..111 garbage, isolated)
#define TQL 30464
#define TKH 60928      // K hi [112 tok][136 ch]
#define TKL 91392
#define TVH 121856     // V^T hi [128 ch][136 key] (keys 98..135 zeroed)
#define TVL 156672
#define ATTN_SMEM 191488

__global__ __launch_bounds__(512, 1)
void attn_kernel()
{
    char* sb = smraw;
    const uint32_t sbase = smem_u32(sb);
    const int b    = blockIdx.x;
    const int tid  = threadIdx.x;
    const int lane = tid & 31;
    const int warp = tid >> 5;
    const int win  = b & (NWIN - 1);

    // ---- zero V^T pad keys 98..135 (both bufs) ----
    for (int i = tid; i < 128 * 38; i += 512) {
        int r = i / 38, c = 98 + (i - (i / 38) * 38);
        *(unsigned short*)(sb + TVH + (r * 136 + c) * 2) = 0;
        *(unsigned short*)(sb + TVL + (r * 136 + c) * 2) = 0;
    }

    // ---- stage Q (scaled), K, V^T in bf16 hi/lo ----
    {
        const float* qk = g_qkv + (size_t)b * N_TOK * 384;
        for (int i = tid; i < N_TOK * 32; i += 512) {
            int m = i >> 5, c = (i & 31) * 4;
            const float* rp = qk + m * 384 + c;
            float4 q = *(const float4*)rp;
            float4 k = *(const float4*)(rp + 128);
            float4 v = *(const float4*)(rp + 256);
            q.x *= SCALE; q.y *= SCALE; q.z *= SCALE; q.w *= SCALE;
            __nv_bfloat16 hh[4], ll[4];
            bf16split(q.x, hh[0], ll[0]); bf16split(q.y, hh[1], ll[1]);
            bf16split(q.z, hh[2], ll[2]); bf16split(q.w, hh[3], ll[3]);
            *(uint2*)(sb + TQH + (m * 136 + c) * 2) = *(uint2*)hh;
            *(uint2*)(sb + TQL + (m * 136 + c) * 2) = *(uint2*)ll;
            bf16split(k.x, hh[0], ll[0]); bf16split(k.y, hh[1], ll[1]);
            bf16split(k.z, hh[2], ll[2]); bf16split(k.w, hh[3], ll[3]);
            *(uint2*)(sb + TKH + (m * 136 + c) * 2) = *(uint2*)hh;
            *(uint2*)(sb + TKL + (m * 136 + c) * 2) = *(uint2*)ll;
            float vf[4] = {v.x, v.y, v.z, v.w};
#pragma unroll
            for (int j = 0; j < 4; j++) {
                __nv_bfloat16 vh, vl;
                bf16split(vf[j], vh, vl);
                *(__nv_bfloat16*)(sb + TVH + ((c + j) * 136 + m) * 2) = vh;
                *(__nv_bfloat16*)(sb + TVL + ((c + j) * 136 + m) * 2) = vl;
            }
        }
    }
    __syncthreads();

    const int a_rp = lane & 15;
    const int a_cs = (lane >> 4) * 8;
    const int b_i  = lane >> 3;
    const int b_rp = (b_i >> 1) * 8 + (lane & 7);
    const int b_cs = (b_i & 1) * 8;
    const int er   = lane >> 2;
    const int ec   = (lane & 3) * 2;

    // items: (h 0..3) x (mt 0..6), one warp each, no further syncs
#pragma unroll 1
    for (int item = warp; item < 28; item += 16) {
        const int h  = item / 7;
        const int mt = item - h * 7;

        // ---- QK^T: full 98(112)-key row block in registers ----
        float acc[14][4];
#pragma unroll
        for (int nt = 0; nt < 14; nt++)
#pragma unroll
            for (int i = 0; i < 4; i++) acc[nt][i] = 0.f;

#pragma unroll
        for (int ks = 0; ks < 2; ks++) {
            const int kb = h * 32 + ks * 16;
            uint32_t ah[4], al[4];
            uint32_t aoff = (uint32_t)((mt * 16 + a_rp) * 136 + kb + a_cs) * 2;
            LDSM_X4(ah[0], ah[1], ah[2], ah[3], sbase + TQH + aoff);
            LDSM_X4(al[0], al[1], al[2], al[3], sbase + TQL + aoff);
#pragma unroll
            for (int np = 0; np < 7; np++) {
                uint32_t boff = (uint32_t)((np * 16 + b_rp) * 136 + kb + b_cs) * 2;
                uint32_t h0, h1, h2, h3, l0, l1, l2, l3;
                LDSM_X4(h0, h1, h2, h3, sbase + TKH + boff);
                LDSM_X4(l0, l1, l2, l3, sbase + TKL + boff);
                MMA_BF16(acc[np * 2],     ah, h0, h1);
                MMA_BF16(acc[np * 2],     al, h0, h1);
                MMA_BF16(acc[np * 2],     ah, l0, l1);
                MMA_BF16(acc[np * 2 + 1], ah, h2, h3);
                MMA_BF16(acc[np * 2 + 1], al, h2, h3);
                MMA_BF16(acc[np * 2 + 1], ah, l2, l3);
            }
        }

        // ---- softmax in registers (rows er and er+8; quad lanes share a row) ----
        const float* combh = g_comb + (size_t)(win * HEADS + h) * N_TOK * N_TOK;
#pragma unroll
        for (int rr = 0; rr < 2; rr++) {
            int n = mt * 16 + er + rr * 8;
            bool rowok = (n < N_TOK);
            int  nc = rowok ? n : 0;
            float mx = -1e30f;
#pragma unroll
            for (int nt = 0; nt < 14; nt++) {
                int m = nt * 8 + ec;
                float v0 = -1e30f, v1 = -1e30f;
                if (m < N_TOK) {   // m even, pair never straddles 98
                    float2 cb = *(const float2*)&combh[nc * N_TOK + m];
                    v0 = acc[nt][rr * 2]     + cb.x;
                    v1 = acc[nt][rr * 2 + 1] + cb.y;
                }
                acc[nt][rr * 2] = v0; acc[nt][rr * 2 + 1] = v1;
                mx = fmaxf(mx, fmaxf(v0, v1));
            }
            mx = fmaxf(mx, __shfl_xor_sync(0xffffffffu, mx, 1));
            mx = fmaxf(mx, __shfl_xor_sync(0xffffffffu, mx, 2));
            float sum = 0.f;
#pragma unroll
            for (int nt = 0; nt < 14; nt++) {
                float e0 = __expf(acc[nt][rr * 2]     - mx);
                float e1 = __expf(acc[nt][rr * 2 + 1] - mx);
                acc[nt][rr * 2] = e0; acc[nt][rr * 2 + 1] = e1;
                sum += e0 + e1;
            }
            sum += __shfl_xor_sync(0xffffffffu, sum, 1);
            sum += __shfl_xor_sync(0xffffffffu, sum, 2);
            float inv = rowok ? __fdividef(1.f, sum) : 0.f;
#pragma unroll
            for (int nt = 0; nt < 14; nt++) {
                acc[nt][rr * 2] *= inv; acc[nt][rr * 2 + 1] *= inv;
            }
        }

        // ---- PV: P from registers (C-frag == A-frag), V^T hi/lo from smem ----
        float oacc[4][4];
#pragma unroll
        for (int nt = 0; nt < 4; nt++)
#pragma unroll
            for (int i = 0; i < 4; i++) oacc[nt][i] = 0.f;

#pragma unroll
        for (int t = 0; t < 7; t++) {
            uint32_t ph[4], pl[4];
            ph[0] = pack_split(acc[2*t][0],   acc[2*t][1],   pl[0]);
            ph[1] = pack_split(acc[2*t][2],   acc[2*t][3],   pl[1]);
            ph[2] = pack_split(acc[2*t+1][0], acc[2*t+1][1], pl[2]);
            ph[3] = pack_split(acc[2*t+1][2], acc[2*t+1][3], pl[3]);
            const int kb = t * 16;
#pragma unroll
            for (int np = 0; np < 2; np++) {
                uint32_t boff = (uint32_t)((h * 32 + np * 16 + b_rp) * 136 + kb + b_cs) * 2;
                uint32_t h0, h1, h2, h3, l0, l1, l2, l3;
                LDSM_X4(h0, h1, h2, h3, sbase + TVH + boff);
                LDSM_X4(l0, l1, l2, l3, sbase + TVL + boff);
                MMA_BF16(oacc[np * 2],     ph, h0, h1);
                MMA_BF16(oacc[np * 2],     pl, h0, h1);
                MMA_BF16(oacc[np * 2],     ph, l0, l1);
                MMA_BF16(oacc[np * 2 + 1], ph, h2, h3);
                MMA_BF16(oacc[np * 2 + 1], pl, h2, h3);
                MMA_BF16(oacc[np * 2 + 1], ph, l2, l3);
            }
        }

        // ---- store O ----
        const int n0 = mt * 16 + er;
#pragma unroll
        for (int nt = 0; nt < 4; nt++) {
            int ch = h * 32 + nt * 8 + ec;
            if (n0 < N_TOK)
                *(float2*)&g_o[((size_t)b * N_TOK + n0) * 128 + ch] =
                    make_float2(oacc[nt][0], oacc[nt][1]);
            if (n0 + 8 < N_TOK)
                *(float2*)&g_o[((size_t)b * N_TOK + n0 + 8) * 128 + ch] =
                    make_float2(oacc[nt][2], oacc[nt][3]);
        }
    }
}

// ======================= launch =======================
extern "C" void kernel_launch(void* const* d_in, const int* in_sizes, int n_in,
                              void* d_out, int out_size)
{
    const float* x          = (const float*)d_in[0];
    const float* mask       = (const float*)d_in[1];
    const float* qkv_w      = (const float*)d_in[2];
    const float* qkv_b      = (const float*)d_in[3];
    const float* proj_w     = (const float*)d_in[4];
    const float* proj_b     = (const float*)d_in[5];
    const float* bias_table = (const float*)d_in[6];
    const int*   rel_idx    = (const int*)d_in[7];
    float*       out        = (float*)d_out;

    const int B    = in_sizes[0] / (N_TOK * DIM);
    const int Mtot = B * N_TOK;
    const int mtiles = (Mtot + 127) / 128;

    float *qkv_ptr, *o_ptr;
    cudaGetSymbolAddress((void**)&qkv_ptr, g_qkv);
    cudaGetSymbolAddress((void**)&o_ptr, g_o);

    cudaFuncSetAttribute(gemm_bf16x3,
                         cudaFuncAttributeMaxDynamicSharedMemorySize, G_SMEM_BYTES);
    cudaFuncSetAttribute(attn_kernel,
                         cudaFuncAttributeMaxDynamicSharedMemorySize, ATTN_SMEM);

    {
        const int total = NWIN * HEADS * N_TOK * N_TOK;
        comb_kernel<<<(total + 255) / 256, 256>>>(mask, bias_table, rel_idx);
    }
    gemm_bf16x3<<<dim3(mtiles, 3), 256, G_SMEM_BYTES>>>(x, qkv_w, qkv_b, qkv_ptr, 384, Mtot);
    attn_kernel<<<B, 512, ATTN_SMEM>>>();
    gemm_bf16x3<<<dim3(mtiles, 1), 256, G_SMEM_BYTES>>>(o_ptr, proj_w, proj_b, out, 128, Mtot);
}

// round 8
// speedup vs baseline: 5.8477x; 1.3506x over previous
#include <cuda_runtime.h>
#include <cuda_bf16.h>
#include <cstdint>

#define N_TOK 98
#define DIM   128
#define HEADS 4
#define NWIN  64
#define SCALE 0.17677669529663687f

#define MAX_B    2048
#define MAX_MTOT (MAX_B * N_TOK)

__device__ float g_qkv[(size_t)MAX_MTOT * 384];
__device__ float g_o[(size_t)MAX_MTOT * 128];
__device__ float g_comb[NWIN * HEADS * N_TOK * N_TOK];

// ======================= helpers =======================
static __device__ __forceinline__ uint32_t smem_u32(const void* p) {
    uint32_t a;
    asm("{ .reg .u64 t; cvta.to.shared.u64 t, %1; cvt.u32.u64 %0, t; }" : "=r"(a) : "l"(p));
    return a;
}
#define LDSM_X4(r0, r1, r2, r3, addr)                                          \
    asm volatile("ldmatrix.sync.aligned.m8n8.x4.shared.b16 {%0,%1,%2,%3}, [%4];" \
                 : "=r"(r0), "=r"(r1), "=r"(r2), "=r"(r3) : "r"(addr))
#define LDSM_X4_T(r0, r1, r2, r3, addr)                                        \
    asm volatile("ldmatrix.sync.aligned.m8n8.x4.trans.shared.b16 {%0,%1,%2,%3}, [%4];" \
                 : "=r"(r0), "=r"(r1), "=r"(r2), "=r"(r3) : "r"(addr))
#define MMA_BF16(c, a, b0, b1)                                                 \
    asm volatile("mma.sync.aligned.m16n8k16.row.col.f32.bf16.bf16.f32 "        \
                 "{%0,%1,%2,%3}, {%4,%5,%6,%7}, {%8,%9}, {%0,%1,%2,%3};"       \
                 : "+f"((c)[0]), "+f"((c)[1]), "+f"((c)[2]), "+f"((c)[3])      \
                 : "r"((a)[0]), "r"((a)[1]), "r"((a)[2]), "r"((a)[3]),         \
                   "r"(b0), "r"(b1))

static __device__ __forceinline__ void bf16split(float a, __nv_bfloat16& h, __nv_bfloat16& l) {
    h = __float2bfloat16_rn(a);
    l = __float2bfloat16_rn(a - __bfloat162float(h));
}
static __device__ __forceinline__ uint32_t pack_split(float a, float b, uint32_t& lo) {
    __nv_bfloat16 ah, al, bh, bl;
    bf16split(a, ah, al); bf16split(b, bh, bl);
    uint16_t ahu = *(uint16_t*)&ah, alu = *(uint16_t*)&al;
    uint16_t bhu = *(uint16_t*)&bh, blu = *(uint16_t*)&bl;
    lo = ((uint32_t)blu << 16) | alu;
    return ((uint32_t)bhu << 16) | ahu;
}

extern __shared__ char smraw[];

// ======================= bf16x3 GEMM: Out[M,N] = A[M,128] @ W[N,128]^T + bias =======================
#define G_AHI 0
#define G_ALO 34816
#define G_WHI 69632
#define G_WLO 88064
#define G_SMEM_BYTES 106496

__global__ __launch_bounds__(256, 2)
void gemm_bf16x3(const float* __restrict__ A,
                 const float* __restrict__ W,
                 const float* __restrict__ bias,
                 float* __restrict__ Out,
                 int Nout, int Mtot)
{
    __nv_bfloat16* sb = (__nv_bfloat16*)smraw;
    const uint32_t sbase = smem_u32(sb);
    const int tid  = threadIdx.x;
    const int lane = tid & 31;
    const int warp = tid >> 5;
    const int wm   = warp & 3;
    const int wn   = warp >> 2;
    const long row0 = (long)blockIdx.x * 128;
    const int  col0 = blockIdx.y * 128;

    // ---- stage A [128 x 128] -> hi/lo bf16, stride 136 ----
#pragma unroll 4
    for (int jj = 0; jj < 16; jj++) {
        int lin = tid + jj * 256;
        int r = lin >> 5, c = (lin & 31) * 4;
        float4 v = make_float4(0.f, 0.f, 0.f, 0.f);
        if (row0 + r < Mtot) v = *(const float4*)&A[(row0 + r) * 128 + c];
        __nv_bfloat16 h0, l0, h1, l1, h2, l2, h3, l3;
        bf16split(v.x, h0, l0); bf16split(v.y, h1, l1);
        bf16split(v.z, h2, l2); bf16split(v.w, h3, l3);
        int o = r * 136 + c;
        sb[(G_AHI>>1) + o] = h0; sb[(G_AHI>>1) + o + 1] = h1; sb[(G_AHI>>1) + o + 2] = h2; sb[(G_AHI>>1) + o + 3] = h3;
        sb[(G_ALO>>1) + o] = l0; sb[(G_ALO>>1) + o + 1] = l1; sb[(G_ALO>>1) + o + 2] = l2; sb[(G_ALO>>1) + o + 3] = l3;
    }

    float acc[2][8][4];
#pragma unroll
    for (int mt = 0; mt < 2; mt++)
#pragma unroll
        for (int nt = 0; nt < 8; nt++)
#pragma unroll
            for (int i = 0; i < 4; i++) acc[mt][nt][i] = 0.f;

    const int a_row = wm * 32 + (lane & 15);
    const int a_cs  = (lane >> 4) * 8;
    const int b_i   = lane >> 3;
    const int b_rp  = (b_i >> 1) * 8 + (lane & 7);
    const int b_cs  = (b_i & 1) * 8;

#pragma unroll 1
    for (int kc = 0; kc < 2; kc++) {
        __syncthreads();
#pragma unroll
        for (int jj = 0; jj < 8; jj++) {
            int lin = tid + jj * 256;
            int r = lin >> 4, c = (lin & 15) * 4;
            float4 v = *(const float4*)&W[(size_t)(col0 + r) * 128 + kc * 64 + c];
            __nv_bfloat16 h0, l0, h1, l1, h2, l2, h3, l3;
        bf16split(v.x, h0, l0); bf16split(v.y, h1, l1);
        bf16split(v.z, h2, l2); bf16split(v.w, h3, l3);
            int o = r * 72 + c;
            sb[(G_WHI>>1) + o] = h0; sb[(G_WHI>>1) + o + 1] = h1; sb[(G_WHI>>1) + o + 2] = h2; sb[(G_WHI>>1) + o + 3] = h3;
            sb[(G_WLO>>1) + o] = l0; sb[(G_WLO>>1) + o + 1] = l1; sb[(G_WLO>>1) + o + 2] = l2; sb[(G_WLO>>1) + o + 3] = l3;
        }
        __syncthreads();

#pragma unroll
        for (int ks = 0; ks < 4; ks++) {
            uint32_t ah[2][4], al[2][4];
#pragma unroll
            for (int mt = 0; mt < 2; mt++) {
                uint32_t off = (uint32_t)((a_row + mt * 16) * 136 + kc * 64 + ks * 16 + a_cs) * 2;
                LDSM_X4(ah[mt][0], ah[mt][1], ah[mt][2], ah[mt][3], sbase + G_AHI + off);
                LDSM_X4(al[mt][0], al[mt][1], al[mt][2], al[mt][3], sbase + G_ALO + off);
            }
#pragma unroll
            for (int np = 0; np < 4; np++) {
                uint32_t off = (uint32_t)((wn * 64 + np * 16 + b_rp) * 72 + ks * 16 + b_cs) * 2;
                uint32_t h0, h1, h2, h3, l0, l1, l2, l3;
                LDSM_X4(h0, h1, h2, h3, sbase + G_WHI + off);
                LDSM_X4(l0, l1, l2, l3, sbase + G_WLO + off);
#pragma unroll
                for (int mt = 0; mt < 2; mt++) {
                    MMA_BF16(acc[mt][np * 2],     ah[mt], h0, h1);
                    MMA_BF16(acc[mt][np * 2],     al[mt], h0, h1);
                    MMA_BF16(acc[mt][np * 2],     ah[mt], l0, l1);
                    MMA_BF16(acc[mt][np * 2 + 1], ah[mt], h2, h3);
                    MMA_BF16(acc[mt][np * 2 + 1], al[mt], h2, h3);
                    MMA_BF16(acc[mt][np * 2 + 1], ah[mt], l2, l3);
                }
            }
        }
    }

    const int er = lane >> 2;
    const int ec = (lane & 3) * 2;
#pragma unroll
    for (int mt = 0; mt < 2; mt++) {
        long r = row0 + wm * 32 + mt * 16 + er;
#pragma unroll
        for (int nt = 0; nt < 8; nt++) {
            int c = col0 + wn * 64 + nt * 8 + ec;
            float b0 = bias[c], b1 = bias[c + 1];
            if (r < Mtot)
                *(float2*)&Out[r * Nout + c] =
                    make_float2(acc[mt][nt][0] + b0, acc[mt][nt][1] + b1);
            if (r + 8 < Mtot)
                *(float2*)&Out[(r + 8) * Nout + c] =
                    make_float2(acc[mt][nt][2] + b0, acc[mt][nt][3] + b1);
        }
    }
}

// ======================= comb = bias_table[rel_idx] + mask =======================
__global__ void comb_kernel(const float* __restrict__ mask,
                            const float* __restrict__ bias_table,
                            const int*   __restrict__ rel_idx)
{
    int idx = blockIdx.x * blockDim.x + threadIdx.x;
    const int total = NWIN * HEADS * N_TOK * N_TOK;
    if (idx >= total) return;
    int w   = idx / (HEADS * N_TOK * N_TOK);
    int rem = idx - w * (HEADS * N_TOK * N_TOK);
    int h   = rem / (N_TOK * N_TOK);
    int nm  = rem - h * (N_TOK * N_TOK);
    g_comb[idx] = bias_table[rel_idx[nm] * HEADS + h] + mask[w * (N_TOK * N_TOK) + nm];
}

// ======================= attention v4: register flash, V via ldmatrix.trans =======================
// smem: Q,K,V each [112 tok][136 ch] bf16 hi/lo
#define TQH 0
#define TQL 30464
#define TKH 60928
#define TKL 91392
#define TVH 121856
#define TVL 152320
#define ATTN_SMEM 182784

__global__ __launch_bounds__(512, 1)
void attn_kernel()
{
    char* sb = smraw;
    const uint32_t sbase = smem_u32(sb);
    const int b    = blockIdx.x;
    const int tid  = threadIdx.x;
    const int lane = tid & 31;
    const int warp = tid >> 5;
    const int win  = b & (NWIN - 1);

    // ---- zero V pad rows 98..111 (hi/lo): P=0 there, but 0*NaN must not happen ----
    for (int i = tid; i < 14 * 68; i += 512) {
        int r = 98 + i / 68, c4 = (i % 68) * 2;
        *(uint32_t*)(sb + TVH + (r * 136 + c4) * 2) = 0u;
        *(uint32_t*)(sb + TVL + (r * 136 + c4) * 2) = 0u;
    }

    // ---- stage Q (scaled), K, V row-major bf16 hi/lo (conflict-free uint2 stores) ----
    {
        const float* qk = g_qkv + (size_t)b * N_TOK * 384;
        for (int i = tid; i < N_TOK * 32; i += 512) {
            int m = i >> 5, c = (i & 31) * 4;
            const float* rp = qk + m * 384 + c;
            float4 q = *(const float4*)rp;
            float4 k = *(const float4*)(rp + 128);
            float4 v = *(const float4*)(rp + 256);
            q.x *= SCALE; q.y *= SCALE; q.z *= SCALE; q.w *= SCALE;
            __nv_bfloat16 hh[4], ll[4];
            bf16split(q.x, hh[0], ll[0]); bf16split(q.y, hh[1], ll[1]);
            bf16split(q.z, hh[2], ll[2]); bf16split(q.w, hh[3], ll[3]);
            *(uint2*)(sb + TQH + (m * 136 + c) * 2) = *(uint2*)hh;
            *(uint2*)(sb + TQL + (m * 136 + c) * 2) = *(uint2*)ll;
            bf16split(k.x, hh[0], ll[0]); bf16split(k.y, hh[1], ll[1]);
            bf16split(k.z, hh[2], ll[2]); bf16split(k.w, hh[3], ll[3]);
            *(uint2*)(sb + TKH + (m * 136 + c) * 2) = *(uint2*)hh;
            *(uint2*)(sb + TKL + (m * 136 + c) * 2) = *(uint2*)ll;
            bf16split(v.x, hh[0], ll[0]); bf16split(v.y, hh[1], ll[1]);
            bf16split(v.z, hh[2], ll[2]); bf16split(v.w, hh[3], ll[3]);
            *(uint2*)(sb + TVH + (m * 136 + c) * 2) = *(uint2*)hh;
            *(uint2*)(sb + TVL + (m * 136 + c) * 2) = *(uint2*)ll;
        }
    }
    __syncthreads();

    const int a_rp = lane & 15;
    const int a_cs = (lane >> 4) * 8;
    const int b_i  = lane >> 3;
    const int b_rp = (b_i >> 1) * 8 + (lane & 7);
    const int b_cs = (b_i & 1) * 8;
    // trans B-frag lane mapping (V: stored [key][ch])
    const int t_rp = (b_i & 1) * 8 + (lane & 7);   // key within 16-block
    const int t_cs = (b_i >> 1) * 8;               // ch within 16-block
    const int er   = lane >> 2;
    const int ec   = (lane & 3) * 2;

#pragma unroll 1
    for (int item = warp; item < 28; item += 16) {
        const int h  = item / 7;
        const int mt = item - h * 7;

        // ---- QK^T ----
        float acc[14][4];
#pragma unroll
        for (int nt = 0; nt < 14; nt++)
#pragma unroll
            for (int i = 0; i < 4; i++) acc[nt][i] = 0.f;

#pragma unroll
        for (int ks = 0; ks < 2; ks++) {
            const int kb = h * 32 + ks * 16;
            uint32_t ah[4], al[4];
            uint32_t aoff = (uint32_t)((mt * 16 + a_rp) * 136 + kb + a_cs) * 2;
            LDSM_X4(ah[0], ah[1], ah[2], ah[3], sbase + TQH + aoff);
            LDSM_X4(al[0], al[1], al[2], al[3], sbase + TQL + aoff);
#pragma unroll
            for (int np = 0; np < 7; np++) {
                uint32_t boff = (uint32_t)((np * 16 + b_rp) * 136 + kb + b_cs) * 2;
                uint32_t h0, h1, h2, h3, l0, l1, l2, l3;
                LDSM_X4(h0, h1, h2, h3, sbase + TKH + boff);
                LDSM_X4(l0, l1, l2, l3, sbase + TKL + boff);
                MMA_BF16(acc[np * 2],     ah, h0, h1);
                MMA_BF16(acc[np * 2],     al, h0, h1);
                MMA_BF16(acc[np * 2],     ah, l0, l1);
                MMA_BF16(acc[np * 2 + 1], ah, h2, h3);
                MMA_BF16(acc[np * 2 + 1], al, h2, h3);
                MMA_BF16(acc[np * 2 + 1], ah, l2, l3);
            }
        }

        // ---- softmax in registers ----
        const float* combh = g_comb + (size_t)(win * HEADS + h) * N_TOK * N_TOK;
#pragma unroll
        for (int rr = 0; rr < 2; rr++) {
            int n = mt * 16 + er + rr * 8;
            bool rowok = (n < N_TOK);
            int  nc = rowok ? n : 0;
            float mx = -1e30f;
#pragma unroll
            for (int nt = 0; nt < 14; nt++) {
                int m = nt * 8 + ec;
                float v0 = -1e30f, v1 = -1e30f;
                if (m < N_TOK) {
                    float2 cb = *(const float2*)&combh[nc * N_TOK + m];
                    v0 = acc[nt][rr * 2]     + cb.x;
                    v1 = acc[nt][rr * 2 + 1] + cb.y;
                }
                acc[nt][rr * 2] = v0; acc[nt][rr * 2 + 1] = v1;
                mx = fmaxf(mx, fmaxf(v0, v1));
            }
            mx = fmaxf(mx, __shfl_xor_sync(0xffffffffu, mx, 1));
            mx = fmaxf(mx, __shfl_xor_sync(0xffffffffu, mx, 2));
            float sum = 0.f;
#pragma unroll
            for (int nt = 0; nt < 14; nt++) {
                float e0 = __expf(acc[nt][rr * 2]     - mx);
                float e1 = __expf(acc[nt][rr * 2 + 1] - mx);
                acc[nt][rr * 2] = e0; acc[nt][rr * 2 + 1] = e1;
                sum += e0 + e1;
            }
            sum += __shfl_xor_sync(0xffffffffu, sum, 1);
            sum += __shfl_xor_sync(0xffffffffu, sum, 2);
            float inv = rowok ? __fdividef(1.f, sum) : 0.f;
#pragma unroll
            for (int nt = 0; nt < 14; nt++) {
                acc[nt][rr * 2] *= inv; acc[nt][rr * 2 + 1] *= inv;
            }
        }

        // ---- PV: P in registers, V B-frag via ldmatrix.trans on [key][ch] ----
        float oacc[4][4];
#pragma unroll
        for (int nt = 0; nt < 4; nt++)
#pragma unroll
            for (int i = 0; i < 4; i++) oacc[nt][i] = 0.f;

#pragma unroll
        for (int t = 0; t < 7; t++) {
            uint32_t ph[4], pl[4];
            ph[0] = pack_split(acc[2*t][0],   acc[2*t][1],   pl[0]);
            ph[1] = pack_split(acc[2*t][2],   acc[2*t][3],   pl[1]);
            ph[2] = pack_split(acc[2*t+1][0], acc[2*t+1][1], pl[2]);
            ph[3] = pack_split(acc[2*t+1][2], acc[2*t+1][3], pl[3]);
#pragma unroll
            for (int np = 0; np < 2; np++) {
                uint32_t boff = (uint32_t)((t * 16 + t_rp) * 136 + h * 32 + np * 16 + t_cs) * 2;
                uint32_t h0, h1, h2, h3, l0, l1, l2, l3;
                LDSM_X4_T(h0, h1, h2, h3, sbase + TVH + boff);
                LDSM_X4_T(l0, l1, l2, l3, sbase + TVL + boff);
                MMA_BF16(oacc[np * 2],     ph, h0, h1);
                MMA_BF16(oacc[np * 2],     pl, h0, h1);
                MMA_BF16(oacc[np * 2],     ph, l0, l1);
                MMA_BF16(oacc[np * 2 + 1], ph, h2, h3);
                MMA_BF16(oacc[np * 2 + 1], pl, h2, h3);
                MMA_BF16(oacc[np * 2 + 1], ph, l2, l3);
            }
        }

        // ---- store O ----
        const int n0 = mt * 16 + er;
#pragma unroll
        for (int nt = 0; nt < 4; nt++) {
            int ch = h * 32 + nt * 8 + ec;
            if (n0 < N_TOK)
                *(float2*)&g_o[((size_t)b * N_TOK + n0) * 128 + ch] =
                    make_float2(oacc[nt][0], oacc[nt][1]);
            if (n0 + 8 < N_TOK)
                *(float2*)&g_o[((size_t)b * N_TOK + n0 + 8) * 128 + ch] =
                    make_float2(oacc[nt][2], oacc[nt][3]);
        }
    }
}

// ======================= launch =======================
extern "C" void kernel_launch(void* const* d_in, const int* in_sizes, int n_in,
                              void* d_out, int out_size)
{
    const float* x          = (const float*)d_in[0];
    const float* mask       = (const float*)d_in[1];
    const float* qkv_w      = (const float*)d_in[2];
    const float* qkv_b      = (const float*)d_in[3];
    const float* proj_w     = (const float*)d_in[4];
    const float* proj_b     = (const float*)d_in[5];
    const float* bias_table = (const float*)d_in[6];
    const int*   rel_idx    = (const int*)d_in[7];
    float*       out        = (float*)d_out;

    const int B    = in_sizes[0] / (N_TOK * DIM);
    const int Mtot = B * N_TOK;
    const int mtiles = (Mtot + 127) / 128;

    float *qkv_ptr, *o_ptr;
    cudaGetSymbolAddress((void**)&qkv_ptr, g_qkv);
    cudaGetSymbolAddress((void**)&o_ptr, g_o);

    cudaFuncSetAttribute(gemm_bf16x3,
                         cudaFuncAttributeMaxDynamicSharedMemorySize, G_SMEM_BYTES);
    cudaFuncSetAttribute(attn_kernel,
                         cudaFuncAttributeMaxDynamicSharedMemorySize, ATTN_SMEM);

    {
        const int total = NWIN * HEADS * N_TOK * N_TOK;
        comb_kernel<<<(total + 255) / 256, 256>>>(mask, bias_table, rel_idx);
    }
    gemm_bf16x3<<<dim3(mtiles, 3), 256, G_SMEM_BYTES>>>(x, qkv_w, qkv_b, qkv_ptr, 384, Mtot);
    attn_kernel<<<B, 512, ATTN_SMEM>>>();
    gemm_bf16x3<<<dim3(mtiles, 1), 256, G_SMEM_BYTES>>>(o_ptr, proj_w, proj_b, out, 128, Mtot);
}